// round 1
// baseline (speedup 1.0000x reference)
#include <cuda_runtime.h>
#include <cstddef>

#define D_MODEL 1024
#define NUM_HEADS 16
#define DEPTH 64
#define BATCH 4
#define SEQ 2048
#define BHN (BATCH * NUM_HEADS)

// Scratch (device globals; no allocation allowed)
__device__ float g_Q[(size_t)BHN * SEQ * DEPTH];     // (b,h,s,d)
__device__ float g_K[(size_t)BHN * SEQ * DEPTH];
__device__ float g_V[(size_t)BHN * SEQ * DEPTH];
__device__ float g_CTX[(size_t)BATCH * SEQ * D_MODEL]; // (b,s,h*64+d)

// ---------------------------------------------------------------------------
// GEMM: C = A(MxK) @ W(NxK)^T + bias.  HEADMAJOR epilogue scatters to (b,h,s,d).
// 128x128 tile, BK=16, 256 threads, 8x8 per thread.
// ---------------------------------------------------------------------------
template <int HEADMAJOR>
__global__ void __launch_bounds__(256)
gemm_bias_kernel(const float* __restrict__ A, const float* __restrict__ W,
                 const float* __restrict__ bias, float* __restrict__ C,
                 int M, int N, int K)
{
    const int BM = 128, BN = 128, BK = 16;
    __shared__ float As[BK][BM];
    __shared__ float Bs[BK][BN];

    const int m0 = blockIdx.y * BM;
    const int n0 = blockIdx.x * BN;
    const int t  = threadIdx.x;
    const int tr = t >> 4;        // 0..15
    const int tc = t & 15;        // 0..15

    float acc[8][8];
#pragma unroll
    for (int i = 0; i < 8; i++)
#pragma unroll
        for (int j = 0; j < 8; j++) acc[i][j] = 0.f;

    for (int k0 = 0; k0 < K; k0 += BK) {
        // A tile: 128x16 = 512 float4 slots, 2 per thread, transpose into As[k][m]
#pragma unroll
        for (int i = 0; i < 2; i++) {
            int slot = t + i * 256;
            int row  = slot >> 2;
            int c4   = (slot & 3) << 2;
            float4 a = *(const float4*)&A[(size_t)(m0 + row) * K + k0 + c4];
            As[c4 + 0][row] = a.x; As[c4 + 1][row] = a.y;
            As[c4 + 2][row] = a.z; As[c4 + 3][row] = a.w;
            float4 b = *(const float4*)&W[(size_t)(n0 + row) * K + k0 + c4];
            Bs[c4 + 0][row] = b.x; Bs[c4 + 1][row] = b.y;
            Bs[c4 + 2][row] = b.z; Bs[c4 + 3][row] = b.w;
        }
        __syncthreads();

#pragma unroll
        for (int kk = 0; kk < BK; kk++) {
            float ra[8], rb[8];
#pragma unroll
            for (int i = 0; i < 8; i++) ra[i] = As[kk][tr * 8 + i];
#pragma unroll
            for (int j = 0; j < 8; j++) rb[j] = Bs[kk][tc * 8 + j];
#pragma unroll
            for (int i = 0; i < 8; i++)
#pragma unroll
                for (int j = 0; j < 8; j++) acc[i][j] += ra[i] * rb[j];
        }
        __syncthreads();
    }

#pragma unroll
    for (int i = 0; i < 8; i++) {
        int m = m0 + tr * 8 + i;
#pragma unroll
        for (int j = 0; j < 8; j++) {
            int n = n0 + tc * 8 + j;
            float v = acc[i][j] + bias[n];
            if (HEADMAJOR) {
                int b = m >> 11;        // m / SEQ
                int s = m & (SEQ - 1);
                int h = n >> 6;         // n / DEPTH
                int d = n & (DEPTH - 1);
                C[(((size_t)(b * NUM_HEADS + h)) * SEQ + s) * DEPTH + d] = v;
            } else {
                C[(size_t)m * N + n] = v;
            }
        }
    }
}

// ---------------------------------------------------------------------------
// logits[bh, q, k] = (Q[bh,q,:] . K[bh,k,:]) / 8 + mask[q,k] * (-1e9)
// Written (unnormalized) directly into the attn output slab.
// ---------------------------------------------------------------------------
__global__ void __launch_bounds__(256)
logits_kernel(const float* __restrict__ Q, const float* __restrict__ Kmat,
              const float* __restrict__ mask, float* __restrict__ attn)
{
    const int BM = 128, BN = 128, BK = 16;
    __shared__ float As[BK][BM];
    __shared__ float Bs[BK][BN];

    const int bh = blockIdx.z;
    const float* Ab = Q    + (size_t)bh * SEQ * DEPTH;
    const float* Bb = Kmat + (size_t)bh * SEQ * DEPTH;
    const int m0 = blockIdx.y * BM;
    const int n0 = blockIdx.x * BN;
    const int t  = threadIdx.x;
    const int tr = t >> 4, tc = t & 15;

    float acc[8][8];
#pragma unroll
    for (int i = 0; i < 8; i++)
#pragma unroll
        for (int j = 0; j < 8; j++) acc[i][j] = 0.f;

#pragma unroll
    for (int k0 = 0; k0 < DEPTH; k0 += BK) {
#pragma unroll
        for (int i = 0; i < 2; i++) {
            int slot = t + i * 256;
            int row  = slot >> 2;
            int c4   = (slot & 3) << 2;
            float4 a = *(const float4*)&Ab[(size_t)(m0 + row) * DEPTH + k0 + c4];
            As[c4 + 0][row] = a.x; As[c4 + 1][row] = a.y;
            As[c4 + 2][row] = a.z; As[c4 + 3][row] = a.w;
            float4 b = *(const float4*)&Bb[(size_t)(n0 + row) * DEPTH + k0 + c4];
            Bs[c4 + 0][row] = b.x; Bs[c4 + 1][row] = b.y;
            Bs[c4 + 2][row] = b.z; Bs[c4 + 3][row] = b.w;
        }
        __syncthreads();
#pragma unroll
        for (int kk = 0; kk < BK; kk++) {
            float ra[8], rb[8];
#pragma unroll
            for (int i = 0; i < 8; i++) ra[i] = As[kk][tr * 8 + i];
#pragma unroll
            for (int j = 0; j < 8; j++) rb[j] = Bs[kk][tc * 8 + j];
#pragma unroll
            for (int i = 0; i < 8; i++)
#pragma unroll
                for (int j = 0; j < 8; j++) acc[i][j] += ra[i] * rb[j];
        }
        __syncthreads();
    }

    float* outb = attn + (size_t)bh * SEQ * SEQ;
#pragma unroll
    for (int i = 0; i < 8; i++) {
        int qg = m0 + tr * 8 + i;
#pragma unroll
        for (int j = 0; j < 8; j++) {
            int kg = n0 + tc * 8 + j;
            float v = acc[i][j] * 0.125f + mask[(size_t)qg * SEQ + kg] * (-1e9f);
            outb[(size_t)qg * SEQ + kg] = v;
        }
    }
}

// ---------------------------------------------------------------------------
// In-place row softmax over last dim (2048). One block (128 thr) per row.
// ---------------------------------------------------------------------------
__global__ void __launch_bounds__(128)
softmax_kernel(float* __restrict__ attn)
{
    __shared__ float red[128];
    const size_t row = blockIdx.x;
    float4* p = (float4*)(attn + row * (size_t)SEQ);
    const int t = threadIdx.x;

    float4 v[4];
    float m = -1e30f;
#pragma unroll
    for (int i = 0; i < 4; i++) {
        v[i] = p[t + i * 128];
        m = fmaxf(m, fmaxf(fmaxf(v[i].x, v[i].y), fmaxf(v[i].z, v[i].w)));
    }
    red[t] = m;
    __syncthreads();
    for (int off = 64; off > 0; off >>= 1) {
        if (t < off) red[t] = fmaxf(red[t], red[t + off]);
        __syncthreads();
    }
    m = red[0];
    __syncthreads();

    float s = 0.f;
#pragma unroll
    for (int i = 0; i < 4; i++) {
        v[i].x = __expf(v[i].x - m); v[i].y = __expf(v[i].y - m);
        v[i].z = __expf(v[i].z - m); v[i].w = __expf(v[i].w - m);
        s += v[i].x + v[i].y + v[i].z + v[i].w;
    }
    red[t] = s;
    __syncthreads();
    for (int off = 64; off > 0; off >>= 1) {
        if (t < off) red[t] += red[t + off];
        __syncthreads();
    }
    float r = 1.0f / red[0];
#pragma unroll
    for (int i = 0; i < 4; i++) {
        v[i].x *= r; v[i].y *= r; v[i].z *= r; v[i].w *= r;
        p[t + i * 128] = v[i];
    }
}

// ---------------------------------------------------------------------------
// ctx[b,s, h*64+d] = sum_k attn[bh,s,k] * V[bh,k,d].  M=2048, N=64, K=2048.
// Tile 128x64, BK=32, 256 threads, 8x4 per thread.
// ---------------------------------------------------------------------------
__global__ void __launch_bounds__(256)
ctx_kernel(const float* __restrict__ attn, const float* __restrict__ V,
           float* __restrict__ ctx)
{
    const int BM = 128, BK = 32;
    __shared__ float As[BK][BM];   // 16 KB
    __shared__ float Bs[BK][DEPTH]; // 8 KB

    const int bh = blockIdx.z;
    const float* Ab = attn + (size_t)bh * SEQ * SEQ;
    const float* Bb = V    + (size_t)bh * SEQ * DEPTH;
    const int m0 = blockIdx.x * BM;
    const int t  = threadIdx.x;
    const int tr = t >> 4, tc = t & 15;

    float acc[8][4];
#pragma unroll
    for (int i = 0; i < 8; i++)
#pragma unroll
        for (int j = 0; j < 4; j++) acc[i][j] = 0.f;

    for (int k0 = 0; k0 < SEQ; k0 += BK) {
        // A tile: 128x32 = 1024 f4, 4 per thread (transposed)
#pragma unroll
        for (int i = 0; i < 4; i++) {
            int slot = t + i * 256;
            int row  = slot >> 3;
            int c4   = (slot & 7) << 2;
            float4 a = *(const float4*)&Ab[(size_t)(m0 + row) * SEQ + k0 + c4];
            As[c4 + 0][row] = a.x; As[c4 + 1][row] = a.y;
            As[c4 + 2][row] = a.z; As[c4 + 3][row] = a.w;
        }
        // B tile: 32x64 = 512 f4, 2 per thread (direct)
#pragma unroll
        for (int i = 0; i < 2; i++) {
            int slot = t + i * 256;
            int row  = slot >> 4;
            int c4   = (slot & 15) << 2;
            float4 b = *(const float4*)&Bb[(size_t)(k0 + row) * DEPTH + c4];
            Bs[row][c4 + 0] = b.x; Bs[row][c4 + 1] = b.y;
            Bs[row][c4 + 2] = b.z; Bs[row][c4 + 3] = b.w;
        }
        __syncthreads();
#pragma unroll
        for (int kk = 0; kk < BK; kk++) {
            float ra[8], rb[4];
#pragma unroll
            for (int i = 0; i < 8; i++) ra[i] = As[kk][tr * 8 + i];
#pragma unroll
            for (int j = 0; j < 4; j++) rb[j] = Bs[kk][tc * 4 + j];
#pragma unroll
            for (int i = 0; i < 8; i++)
#pragma unroll
                for (int j = 0; j < 4; j++) acc[i][j] += ra[i] * rb[j];
        }
        __syncthreads();
    }

    const int b = bh >> 4;
    const int h = bh & 15;
#pragma unroll
    for (int i = 0; i < 8; i++) {
        int qg = m0 + tr * 8 + i;
#pragma unroll
        for (int j = 0; j < 4; j++) {
            int d = tc * 4 + j;
            ctx[((size_t)b * SEQ + qg) * D_MODEL + h * DEPTH + d] = acc[i][j];
        }
    }
}

// ---------------------------------------------------------------------------
// Inputs (metadata order): v, k, q, mask, wq_w, wq_b, wk_w, wk_b, wv_w, wv_b,
//                          dense_w, dense_b
// Output: [out (B*S*D_MODEL) | attn (B*H*S*S)] fp32
// ---------------------------------------------------------------------------
extern "C" void kernel_launch(void* const* d_in, const int* in_sizes, int n_in,
                              void* d_out, int out_size)
{
    const float* v_in  = (const float*)d_in[0];
    const float* k_in  = (const float*)d_in[1];
    const float* q_in  = (const float*)d_in[2];
    const float* mask  = (const float*)d_in[3];
    const float* wq_w  = (const float*)d_in[4];
    const float* wq_b  = (const float*)d_in[5];
    const float* wk_w  = (const float*)d_in[6];
    const float* wk_b  = (const float*)d_in[7];
    const float* wv_w  = (const float*)d_in[8];
    const float* wv_b  = (const float*)d_in[9];
    const float* dw    = (const float*)d_in[10];
    const float* db    = (const float*)d_in[11];

    float* out  = (float*)d_out;
    float* attn = out + (size_t)BATCH * SEQ * D_MODEL;

    float *gq, *gk, *gv, *gctx;
    cudaGetSymbolAddress((void**)&gq,   g_Q);
    cudaGetSymbolAddress((void**)&gk,   g_K);
    cudaGetSymbolAddress((void**)&gv,   g_V);
    cudaGetSymbolAddress((void**)&gctx, g_CTX);

    const int M = BATCH * SEQ;   // 8192

    dim3 gp(D_MODEL / 128, M / 128);   // (8, 64)
    gemm_bias_kernel<1><<<gp, 256>>>(q_in, wq_w, wq_b, gq, M, D_MODEL, D_MODEL);
    gemm_bias_kernel<1><<<gp, 256>>>(k_in, wk_w, wk_b, gk, M, D_MODEL, D_MODEL);
    gemm_bias_kernel<1><<<gp, 256>>>(v_in, wv_w, wv_b, gv, M, D_MODEL, D_MODEL);

    dim3 gl(SEQ / 128, SEQ / 128, BHN);  // (16,16,64)
    logits_kernel<<<gl, 256>>>(gq, gk, mask, attn);

    softmax_kernel<<<BHN * SEQ, 128>>>(attn);

    dim3 gc(SEQ / 128, 1, BHN);          // (16,1,64)
    ctx_kernel<<<gc, 256>>>(attn, gv, gctx);

    gemm_bias_kernel<0><<<gp, 256>>>(gctx, dw, db, out, M, D_MODEL, D_MODEL);
}

// round 3
// speedup vs baseline: 1.9616x; 1.9616x over previous
#include <cuda_runtime.h>
#include <cstddef>

#define D_MODEL 1024
#define NUM_HEADS 16
#define DEPTH 64
#define BATCH 4
#define SEQ 2048
#define BHN (BATCH * NUM_HEADS)

// Scratch (device globals; no allocation allowed)
__device__ float g_Q[(size_t)BHN * SEQ * DEPTH];       // (b,h,s,d)
__device__ float g_K[(size_t)BHN * SEQ * DEPTH];
__device__ float g_V[(size_t)BHN * SEQ * DEPTH];
__device__ float g_CTX[(size_t)BATCH * SEQ * D_MODEL]; // (b,s,h*64+d)

// ---------------------------------------------------------------------------
// TF32 helpers
// ---------------------------------------------------------------------------
__device__ __forceinline__ unsigned f2tf(float x) {
    unsigned u;
    asm("cvt.rna.tf32.f32 %0, %1;" : "=r"(u) : "f"(x));
    return u;
}

// D += A(16x8) @ B(8x8)  (tf32 in f32 regs, fp32 accum)
__device__ __forceinline__ void mma8(float* d, const unsigned* a, const unsigned* b) {
    asm volatile(
        "mma.sync.aligned.m16n8k8.row.col.f32.tf32.tf32.f32 "
        "{%0,%1,%2,%3}, {%4,%5,%6,%7}, {%8,%9}, {%0,%1,%2,%3};\n"
        : "+f"(d[0]), "+f"(d[1]), "+f"(d[2]), "+f"(d[3])
        : "r"(a[0]), "r"(a[1]), "r"(a[2]), "r"(a[3]), "r"(b[0]), "r"(b[1]));
}

__device__ __forceinline__ void store_hm(float* __restrict__ C, int m, int n, float v) {
    int b = m >> 11, s = m & (SEQ - 1);
    int h = n >> 6, d = n & (DEPTH - 1);
    C[(((size_t)(b * NUM_HEADS + h)) * SEQ + s) * DEPTH + d] = v;
}

// ---------------------------------------------------------------------------
// C = A(MxK) @ W(NxK)^T + bias   (tf32 tensor core)
// Tile 128x128, BK=32, 256 thr (8 warps, 2x4), warp tile 64x32.
// ---------------------------------------------------------------------------
template <int HEADMAJOR>
__global__ void __launch_bounds__(256)
gemm_tf32(const float* __restrict__ A, const float* __restrict__ W,
          const float* __restrict__ bias, float* __restrict__ C,
          int M, int N, int K)
{
    const int BM = 128, BN = 128, BK = 32;
    __shared__ __align__(16) unsigned As[BM][BK + 4];
    __shared__ __align__(16) unsigned Bs[BN][BK + 4];

    const int m0 = blockIdx.y * BM;
    const int n0 = blockIdx.x * BN;
    const int t = threadIdx.x;
    const int warp = t >> 5, lane = t & 31;
    const int wm = (warp >> 2) * 64, wn = (warp & 3) * 32;
    const int gid = lane >> 2, tig = lane & 3;

    float acc[4][4][4];
#pragma unroll
    for (int mi = 0; mi < 4; mi++)
#pragma unroll
        for (int ni = 0; ni < 4; ni++)
#pragma unroll
            for (int r = 0; r < 4; r++) acc[mi][ni][r] = 0.f;

    for (int k0 = 0; k0 < K; k0 += BK) {
#pragma unroll
        for (int i = 0; i < 4; i++) {
            int idx = t + i * 256;              // 0..1023
            int r = idx >> 3;                   // 0..127
            int c4 = (idx & 7) << 2;            // 0,4,..,28
            float4 a = *(const float4*)&A[(size_t)(m0 + r) * K + k0 + c4];
            *(uint4*)&As[r][c4] = make_uint4(f2tf(a.x), f2tf(a.y), f2tf(a.z), f2tf(a.w));
            float4 b = *(const float4*)&W[(size_t)(n0 + r) * K + k0 + c4];
            *(uint4*)&Bs[r][c4] = make_uint4(f2tf(b.x), f2tf(b.y), f2tf(b.z), f2tf(b.w));
        }
        __syncthreads();

#pragma unroll
        for (int kk = 0; kk < BK; kk += 8) {
            unsigned af[4][4], bf[4][2];
#pragma unroll
            for (int mi = 0; mi < 4; mi++) {
                int r = wm + mi * 16 + gid;
                af[mi][0] = As[r][kk + tig];
                af[mi][1] = As[r + 8][kk + tig];
                af[mi][2] = As[r][kk + tig + 4];
                af[mi][3] = As[r + 8][kk + tig + 4];
            }
#pragma unroll
            for (int ni = 0; ni < 4; ni++) {
                int c = wn + ni * 8 + gid;
                bf[ni][0] = Bs[c][kk + tig];
                bf[ni][1] = Bs[c][kk + tig + 4];
            }
#pragma unroll
            for (int mi = 0; mi < 4; mi++)
#pragma unroll
                for (int ni = 0; ni < 4; ni++)
                    mma8(acc[mi][ni], af[mi], bf[ni]);
        }
        __syncthreads();
    }

#pragma unroll
    for (int mi = 0; mi < 4; mi++) {
        int r0 = m0 + wm + mi * 16 + gid;
#pragma unroll
        for (int ni = 0; ni < 4; ni++) {
            int c0 = n0 + wn + ni * 8 + 2 * tig;
            float b0 = bias[c0], b1 = bias[c0 + 1];
            if (HEADMAJOR) {
                store_hm(C, r0,     c0,     acc[mi][ni][0] + b0);
                store_hm(C, r0,     c0 + 1, acc[mi][ni][1] + b1);
                store_hm(C, r0 + 8, c0,     acc[mi][ni][2] + b0);
                store_hm(C, r0 + 8, c0 + 1, acc[mi][ni][3] + b1);
            } else {
                C[(size_t)r0 * N + c0]           = acc[mi][ni][0] + b0;
                C[(size_t)r0 * N + c0 + 1]       = acc[mi][ni][1] + b1;
                C[(size_t)(r0 + 8) * N + c0]     = acc[mi][ni][2] + b0;
                C[(size_t)(r0 + 8) * N + c0 + 1] = acc[mi][ni][3] + b1;
            }
        }
    }
}

// ---------------------------------------------------------------------------
// logits[bh,q,k] = (Q[bh,q,:].K[bh,k,:]) / 8 + mask[q,k]*(-1e9)  (raw, pre-softmax)
// Same tiling as gemm_tf32, K=DEPTH=64.
// ---------------------------------------------------------------------------
__global__ void __launch_bounds__(256)
logits_tf32(const float* __restrict__ Q, const float* __restrict__ Km,
            const float* __restrict__ mask, float* __restrict__ attn)
{
    const int BM = 128, BN = 128, BK = 32;
    __shared__ __align__(16) unsigned As[BM][BK + 4];
    __shared__ __align__(16) unsigned Bs[BN][BK + 4];

    const int bh = blockIdx.z;
    const float* Ab = Q  + (size_t)bh * SEQ * DEPTH;
    const float* Bb = Km + (size_t)bh * SEQ * DEPTH;
    const int m0 = blockIdx.y * BM;
    const int n0 = blockIdx.x * BN;
    const int t = threadIdx.x;
    const int warp = t >> 5, lane = t & 31;
    const int wm = (warp >> 2) * 64, wn = (warp & 3) * 32;
    const int gid = lane >> 2, tig = lane & 3;

    float acc[4][4][4];
#pragma unroll
    for (int mi = 0; mi < 4; mi++)
#pragma unroll
        for (int ni = 0; ni < 4; ni++)
#pragma unroll
            for (int r = 0; r < 4; r++) acc[mi][ni][r] = 0.f;

#pragma unroll
    for (int k0 = 0; k0 < DEPTH; k0 += BK) {
#pragma unroll
        for (int i = 0; i < 4; i++) {
            int idx = t + i * 256;
            int r = idx >> 3;
            int c4 = (idx & 7) << 2;
            float4 a = *(const float4*)&Ab[(size_t)(m0 + r) * DEPTH + k0 + c4];
            *(uint4*)&As[r][c4] = make_uint4(f2tf(a.x), f2tf(a.y), f2tf(a.z), f2tf(a.w));
            float4 b = *(const float4*)&Bb[(size_t)(n0 + r) * DEPTH + k0 + c4];
            *(uint4*)&Bs[r][c4] = make_uint4(f2tf(b.x), f2tf(b.y), f2tf(b.z), f2tf(b.w));
        }
        __syncthreads();
#pragma unroll
        for (int kk = 0; kk < BK; kk += 8) {
            unsigned af[4][4], bf[4][2];
#pragma unroll
            for (int mi = 0; mi < 4; mi++) {
                int r = wm + mi * 16 + gid;
                af[mi][0] = As[r][kk + tig];
                af[mi][1] = As[r + 8][kk + tig];
                af[mi][2] = As[r][kk + tig + 4];
                af[mi][3] = As[r + 8][kk + tig + 4];
            }
#pragma unroll
            for (int ni = 0; ni < 4; ni++) {
                int c = wn + ni * 8 + gid;
                bf[ni][0] = Bs[c][kk + tig];
                bf[ni][1] = Bs[c][kk + tig + 4];
            }
#pragma unroll
            for (int mi = 0; mi < 4; mi++)
#pragma unroll
                for (int ni = 0; ni < 4; ni++)
                    mma8(acc[mi][ni], af[mi], bf[ni]);
        }
        __syncthreads();
    }

    float* outb = attn + (size_t)bh * SEQ * SEQ;
#pragma unroll
    for (int mi = 0; mi < 4; mi++) {
#pragma unroll
        for (int ni = 0; ni < 4; ni++) {
            int c0 = n0 + wn + ni * 8 + 2 * tig;
#pragma unroll
            for (int hrow = 0; hrow < 2; hrow++) {
                int q = m0 + wm + mi * 16 + gid + hrow * 8;
#pragma unroll
                for (int hc = 0; hc < 2; hc++) {
                    int kcol = c0 + hc;
                    float v = acc[mi][ni][hrow * 2 + hc] * 0.125f
                              + mask[(size_t)q * SEQ + kcol] * (-1e9f);
                    outb[(size_t)q * SEQ + kcol] = v;
                }
            }
        }
    }
}

// ---------------------------------------------------------------------------
// In-place row softmax over last dim (2048). One block (128 thr) per row.
// ---------------------------------------------------------------------------
__global__ void __launch_bounds__(128)
softmax_kernel(float* __restrict__ attn)
{
    __shared__ float red[128];
    const size_t row = blockIdx.x;
    float4* p = (float4*)(attn + row * (size_t)SEQ);
    const int t = threadIdx.x;

    float4 v[4];
    float m = -1e30f;
#pragma unroll
    for (int i = 0; i < 4; i++) {
        v[i] = p[t + i * 128];
        m = fmaxf(m, fmaxf(fmaxf(v[i].x, v[i].y), fmaxf(v[i].z, v[i].w)));
    }
    red[t] = m;
    __syncthreads();
    for (int off = 64; off > 0; off >>= 1) {
        if (t < off) red[t] = fmaxf(red[t], red[t + off]);
        __syncthreads();
    }
    m = red[0];
    __syncthreads();

    float s = 0.f;
#pragma unroll
    for (int i = 0; i < 4; i++) {
        v[i].x = __expf(v[i].x - m); v[i].y = __expf(v[i].y - m);
        v[i].z = __expf(v[i].z - m); v[i].w = __expf(v[i].w - m);
        s += v[i].x + v[i].y + v[i].z + v[i].w;
    }
    red[t] = s;
    __syncthreads();
    for (int off = 64; off > 0; off >>= 1) {
        if (t < off) red[t] += red[t + off];
        __syncthreads();
    }
    float r = 1.0f / red[0];
#pragma unroll
    for (int i = 0; i < 4; i++) {
        v[i].x *= r; v[i].y *= r; v[i].z *= r; v[i].w *= r;
        p[t + i * 128] = v[i];
    }
}

// ---------------------------------------------------------------------------
// ctx[b,s,h*64+d] = sum_k attn[bh,s,k] * V[bh,k,d]
// Tile 128x64, BK=32, 8 warps, warp tile 16x64 (1x8 mma tiles).
// ---------------------------------------------------------------------------
__global__ void __launch_bounds__(256)
ctx_tf32(const float* __restrict__ attn, const float* __restrict__ V,
         float* __restrict__ ctx)
{
    const int BM = 128, BK = 32;
    __shared__ __align__(16) unsigned As[BM][BK + 4];
    __shared__ __align__(16) unsigned Bs[DEPTH][BK + 4];

    const int bh = blockIdx.z;
    const float* Ab = attn + (size_t)bh * SEQ * SEQ;
    const float* Bb = V    + (size_t)bh * SEQ * DEPTH;
    const int m0 = blockIdx.x * BM;
    const int t = threadIdx.x;
    const int warp = t >> 5, lane = t & 31;
    const int wm = warp * 16;
    const int gid = lane >> 2, tig = lane & 3;

    float acc[8][4];
#pragma unroll
    for (int ni = 0; ni < 8; ni++)
#pragma unroll
        for (int r = 0; r < 4; r++) acc[ni][r] = 0.f;

    for (int k0 = 0; k0 < SEQ; k0 += BK) {
        // A tile 128x32 (attn rows)
#pragma unroll
        for (int i = 0; i < 4; i++) {
            int idx = t + i * 256;
            int r = idx >> 3;
            int c4 = (idx & 7) << 2;
            float4 a = *(const float4*)&Ab[(size_t)(m0 + r) * SEQ + k0 + c4];
            *(uint4*)&As[r][c4] = make_uint4(f2tf(a.x), f2tf(a.y), f2tf(a.z), f2tf(a.w));
        }
        // B tile: V rows k0..k0+31, all 64 cols; transpose into Bs[d][k]
#pragma unroll
        for (int i = 0; i < 2; i++) {
            int idx = t + i * 256;          // 0..511
            int kr = idx >> 4;              // 0..31
            int d4 = (idx & 15) << 2;       // 0..60
            float4 b = *(const float4*)&Bb[(size_t)(k0 + kr) * DEPTH + d4];
            Bs[d4 + 0][kr] = f2tf(b.x);
            Bs[d4 + 1][kr] = f2tf(b.y);
            Bs[d4 + 2][kr] = f2tf(b.z);
            Bs[d4 + 3][kr] = f2tf(b.w);
        }
        __syncthreads();

#pragma unroll
        for (int kk = 0; kk < BK; kk += 8) {
            unsigned af[4], bf[8][2];
            int r = wm + gid;
            af[0] = As[r][kk + tig];
            af[1] = As[r + 8][kk + tig];
            af[2] = As[r][kk + tig + 4];
            af[3] = As[r + 8][kk + tig + 4];
#pragma unroll
            for (int ni = 0; ni < 8; ni++) {
                int c = ni * 8 + gid;
                bf[ni][0] = Bs[c][kk + tig];
                bf[ni][1] = Bs[c][kk + tig + 4];
            }
#pragma unroll
            for (int ni = 0; ni < 8; ni++)
                mma8(acc[ni], af, bf[ni]);
        }
        __syncthreads();
    }

    const int b = bh >> 4;
    const int h = bh & 15;
#pragma unroll
    for (int ni = 0; ni < 8; ni++) {
        int d0 = ni * 8 + 2 * tig;
        int q0 = m0 + wm + gid;
        ctx[((size_t)b * SEQ + q0) * D_MODEL + h * DEPTH + d0]           = acc[ni][0];
        ctx[((size_t)b * SEQ + q0) * D_MODEL + h * DEPTH + d0 + 1]       = acc[ni][1];
        ctx[((size_t)b * SEQ + q0 + 8) * D_MODEL + h * DEPTH + d0]       = acc[ni][2];
        ctx[((size_t)b * SEQ + q0 + 8) * D_MODEL + h * DEPTH + d0 + 1]   = acc[ni][3];
    }
}

// ---------------------------------------------------------------------------
// Inputs (metadata order): v, k, q, mask, wq_w, wq_b, wk_w, wk_b, wv_w, wv_b,
//                          dense_w, dense_b
// Output: [out (B*S*D_MODEL) | attn (B*H*S*S)] fp32
// ---------------------------------------------------------------------------
extern "C" void kernel_launch(void* const* d_in, const int* in_sizes, int n_in,
                              void* d_out, int out_size)
{
    const float* v_in = (const float*)d_in[0];
    const float* k_in = (const float*)d_in[1];
    const float* q_in = (const float*)d_in[2];
    const float* mask = (const float*)d_in[3];
    const float* wq_w = (const float*)d_in[4];
    const float* wq_b = (const float*)d_in[5];
    const float* wk_w = (const float*)d_in[6];
    const float* wk_b = (const float*)d_in[7];
    const float* wv_w = (const float*)d_in[8];
    const float* wv_b = (const float*)d_in[9];
    const float* dw   = (const float*)d_in[10];
    const float* db   = (const float*)d_in[11];

    float* out  = (float*)d_out;
    float* attn = out + (size_t)BATCH * SEQ * D_MODEL;

    float *gq, *gk, *gv, *gctx;
    cudaGetSymbolAddress((void**)&gq,   g_Q);
    cudaGetSymbolAddress((void**)&gk,   g_K);
    cudaGetSymbolAddress((void**)&gv,   g_V);
    cudaGetSymbolAddress((void**)&gctx, g_CTX);

    const int M = BATCH * SEQ;  // 8192

    dim3 gp(D_MODEL / 128, M / 128);     // (8, 64)
    gemm_tf32<1><<<gp, 256>>>(q_in, wq_w, wq_b, gq, M, D_MODEL, D_MODEL);
    gemm_tf32<1><<<gp, 256>>>(k_in, wk_w, wk_b, gk, M, D_MODEL, D_MODEL);
    gemm_tf32<1><<<gp, 256>>>(v_in, wv_w, wv_b, gv, M, D_MODEL, D_MODEL);

    dim3 gl(SEQ / 128, SEQ / 128, BHN);  // (16,16,64)
    logits_tf32<<<gl, 256>>>(gq, gk, mask, attn);

    softmax_kernel<<<BHN * SEQ, 128>>>(attn);

    dim3 gc(SEQ / 128, 1, BHN);          // (16,1,64)
    ctx_tf32<<<gc, 256>>>(attn, gv, gctx);

    gemm_tf32<0><<<gp, 256>>>(gctx, dw, db, out, M, D_MODEL, D_MODEL);
}

// round 5
// speedup vs baseline: 2.1103x; 1.0758x over previous
#include <cuda_runtime.h>
#include <cstddef>

#define D_MODEL 1024
#define NUM_HEADS 16
#define DEPTH 64
#define BATCH 4
#define SEQ 2048
#define BHN (BATCH * NUM_HEADS)
#define BQ 128
#define KB 64
#define NKB (SEQ / KB)

// Scratch (device globals; no allocation allowed)
__device__ float g_Q[(size_t)BHN * SEQ * DEPTH];       // (b,h,s,d)
__device__ float g_K[(size_t)BHN * SEQ * DEPTH];
__device__ float g_V[(size_t)BHN * SEQ * DEPTH];
__device__ float g_CTX[(size_t)BATCH * SEQ * D_MODEL]; // (b,s,h*64+d)

// ---------------------------------------------------------------------------
// TF32 helpers
// ---------------------------------------------------------------------------
__device__ __forceinline__ unsigned f2tf(float x) {
    unsigned u;
    asm("cvt.rna.tf32.f32 %0, %1;" : "=r"(u) : "f"(x));
    return u;
}

// D += A(16x8) @ B(8x8)  (tf32, fp32 accum)
__device__ __forceinline__ void mma8(float* d, const unsigned* a, const unsigned* b) {
    asm volatile(
        "mma.sync.aligned.m16n8k8.row.col.f32.tf32.tf32.f32 "
        "{%0,%1,%2,%3}, {%4,%5,%6,%7}, {%8,%9}, {%0,%1,%2,%3};\n"
        : "+f"(d[0]), "+f"(d[1]), "+f"(d[2]), "+f"(d[3])
        : "r"(a[0]), "r"(a[1]), "r"(a[2]), "r"(a[3]), "r"(b[0]), "r"(b[1]));
}

__device__ __forceinline__ void store_hm(float* __restrict__ C, int m, int n, float v) {
    int b = m >> 11, s = m & (SEQ - 1);
    int h = n >> 6, d = n & (DEPTH - 1);
    C[(((size_t)(b * NUM_HEADS + h)) * SEQ + s) * DEPTH + d] = v;
}

// ---------------------------------------------------------------------------
// C = A(MxK) @ W(NxK)^T + bias   (tf32 tensor core)  -- projections + dense
// ---------------------------------------------------------------------------
template <int HEADMAJOR>
__global__ void __launch_bounds__(256)
gemm_tf32(const float* __restrict__ A, const float* __restrict__ W,
          const float* __restrict__ bias, float* __restrict__ C,
          int M, int N, int K)
{
    const int BM = 128, BN = 128, BK = 32;
    __shared__ __align__(16) unsigned As[BM][BK + 4];
    __shared__ __align__(16) unsigned Bs[BN][BK + 4];

    const int m0 = blockIdx.y * BM;
    const int n0 = blockIdx.x * BN;
    const int t = threadIdx.x;
    const int warp = t >> 5, lane = t & 31;
    const int wm = (warp >> 2) * 64, wn = (warp & 3) * 32;
    const int gid = lane >> 2, tig = lane & 3;

    float acc[4][4][4];
#pragma unroll
    for (int mi = 0; mi < 4; mi++)
#pragma unroll
        for (int ni = 0; ni < 4; ni++)
#pragma unroll
            for (int r = 0; r < 4; r++) acc[mi][ni][r] = 0.f;

    for (int k0 = 0; k0 < K; k0 += BK) {
#pragma unroll
        for (int i = 0; i < 4; i++) {
            int idx = t + i * 256;
            int r = idx >> 3;
            int c4 = (idx & 7) << 2;
            float4 a = *(const float4*)&A[(size_t)(m0 + r) * K + k0 + c4];
            *(uint4*)&As[r][c4] = make_uint4(f2tf(a.x), f2tf(a.y), f2tf(a.z), f2tf(a.w));
            float4 b = *(const float4*)&W[(size_t)(n0 + r) * K + k0 + c4];
            *(uint4*)&Bs[r][c4] = make_uint4(f2tf(b.x), f2tf(b.y), f2tf(b.z), f2tf(b.w));
        }
        __syncthreads();

#pragma unroll
        for (int kk = 0; kk < BK; kk += 8) {
            unsigned af[4][4], bf[4][2];
#pragma unroll
            for (int mi = 0; mi < 4; mi++) {
                int r = wm + mi * 16 + gid;
                af[mi][0] = As[r][kk + tig];
                af[mi][1] = As[r + 8][kk + tig];
                af[mi][2] = As[r][kk + tig + 4];
                af[mi][3] = As[r + 8][kk + tig + 4];
            }
#pragma unroll
            for (int ni = 0; ni < 4; ni++) {
                int c = wn + ni * 8 + gid;
                bf[ni][0] = Bs[c][kk + tig];
                bf[ni][1] = Bs[c][kk + tig + 4];
            }
#pragma unroll
            for (int mi = 0; mi < 4; mi++)
#pragma unroll
                for (int ni = 0; ni < 4; ni++)
                    mma8(acc[mi][ni], af[mi], bf[ni]);
        }
        __syncthreads();
    }

#pragma unroll
    for (int mi = 0; mi < 4; mi++) {
        int r0 = m0 + wm + mi * 16 + gid;
#pragma unroll
        for (int ni = 0; ni < 4; ni++) {
            int c0 = n0 + wn + ni * 8 + 2 * tig;
            float b0 = bias[c0], b1 = bias[c0 + 1];
            if (HEADMAJOR) {
                store_hm(C, r0,     c0,     acc[mi][ni][0] + b0);
                store_hm(C, r0,     c0 + 1, acc[mi][ni][1] + b1);
                store_hm(C, r0 + 8, c0,     acc[mi][ni][2] + b0);
                store_hm(C, r0 + 8, c0 + 1, acc[mi][ni][3] + b1);
            } else {
                C[(size_t)r0 * N + c0]           = acc[mi][ni][0] + b0;
                C[(size_t)r0 * N + c0 + 1]       = acc[mi][ni][1] + b1;
                C[(size_t)(r0 + 8) * N + c0]     = acc[mi][ni][2] + b0;
                C[(size_t)(r0 + 8) * N + c0 + 1] = acc[mi][ni][3] + b1;
            }
        }
    }
}

// ---------------------------------------------------------------------------
// Fused attention: logits + softmax + attn-write + P@V per 128-row q-block.
// Pass A: online row max/sumexp (no gmem writes).
// Pass B: recompute S (bitwise identical), p = exp(s-m)/l, write attn once,
//         stage P in smem (tf32) and accumulate ctx += P@V on tensor cores.
// ---------------------------------------------------------------------------
struct __align__(16) FusedSmem {
    unsigned Qs[BQ][68];      // q rows x depth
    unsigned Ks[KB][68];      // k rows x depth
    unsigned VTs[DEPTH][68];  // depth x k (transposed)
    unsigned Ps[BQ][68];      // q rows x k (tf32 P for PV mma)
    float row_m[BQ];
    float row_l[BQ];
    float row_scale[BQ];
    float row_inv[BQ];
    float part[BQ][2];
};

__global__ void __launch_bounds__(256, 1)
fused_attn(const float* __restrict__ Q, const float* __restrict__ Kmat,
           const float* __restrict__ V, const float* __restrict__ mask,
           float* __restrict__ attn, float* __restrict__ ctx)
{
    extern __shared__ char smraw[];
    FusedSmem& sm = *(FusedSmem*)smraw;

    const int bh = blockIdx.y;
    const int q0 = blockIdx.x * BQ;
    const float* Qb = Q    + (size_t)bh * SEQ * DEPTH;
    const float* Kb = Kmat + (size_t)bh * SEQ * DEPTH;
    const float* Vb = V    + (size_t)bh * SEQ * DEPTH;
    float* attnb = attn + (size_t)bh * SEQ * SEQ;

    const int t = threadIdx.x;
    const int warp = t >> 5, lane = t & 31;
    const int gid = lane >> 2, tig = lane & 3;
    // S-tile warp layout: 4x2 warps, warp tile 32x32
    const int wmS = (warp >> 1) * 32;
    const int wnS = (warp & 1) * 32;
    const int wcol = warp & 1;

    if (t < BQ) { sm.row_m[t] = -1e30f; sm.row_l[t] = 0.f; }

    // Load Q tile (128 x 64) as tf32
#pragma unroll
    for (int i = 0; i < 8; i++) {
        int idx = t + i * 256;         // 0..2047
        int r = idx >> 4;              // 0..127
        int c4 = (idx & 15) << 2;      // 0..60
        float4 a = *(const float4*)&Qb[(size_t)(q0 + r) * DEPTH + c4];
        *(uint4*)&sm.Qs[r][c4] = make_uint4(f2tf(a.x), f2tf(a.y), f2tf(a.z), f2tf(a.w));
    }
    __syncthreads();

    // ------------------------- Pass A: stats -------------------------
    for (int kb = 0; kb < NKB; kb++) {
        const int k0 = kb * KB;
#pragma unroll
        for (int i = 0; i < 4; i++) {
            int idx = t + i * 256;     // 0..1023
            int r = idx >> 4;          // 0..63
            int c4 = (idx & 15) << 2;
            float4 a = *(const float4*)&Kb[(size_t)(k0 + r) * DEPTH + c4];
            *(uint4*)&sm.Ks[r][c4] = make_uint4(f2tf(a.x), f2tf(a.y), f2tf(a.z), f2tf(a.w));
        }
        __syncthreads();

        float acc[2][4][4];
#pragma unroll
        for (int mi = 0; mi < 2; mi++)
#pragma unroll
            for (int ni = 0; ni < 4; ni++)
#pragma unroll
                for (int r = 0; r < 4; r++) acc[mi][ni][r] = 0.f;

#pragma unroll
        for (int kk = 0; kk < DEPTH; kk += 8) {
            unsigned af[2][4], bf[4][2];
#pragma unroll
            for (int mi = 0; mi < 2; mi++) {
                int r = wmS + mi * 16 + gid;
                af[mi][0] = sm.Qs[r][kk + tig];
                af[mi][1] = sm.Qs[r + 8][kk + tig];
                af[mi][2] = sm.Qs[r][kk + tig + 4];
                af[mi][3] = sm.Qs[r + 8][kk + tig + 4];
            }
#pragma unroll
            for (int ni = 0; ni < 4; ni++) {
                int c = wnS + ni * 8 + gid;
                bf[ni][0] = sm.Ks[c][kk + tig];
                bf[ni][1] = sm.Ks[c][kk + tig + 4];
            }
#pragma unroll
            for (int mi = 0; mi < 2; mi++)
#pragma unroll
                for (int ni = 0; ni < 4; ni++)
                    mma8(acc[mi][ni], af[mi], bf[ni]);
        }

        // scale + mask in-place; per-thread row max
        float rm[4] = {-1e30f, -1e30f, -1e30f, -1e30f};
#pragma unroll
        for (int mi = 0; mi < 2; mi++) {
#pragma unroll
            for (int h = 0; h < 2; h++) {
                int r = wmS + mi * 16 + gid + h * 8;
                int q = q0 + r;
#pragma unroll
                for (int ni = 0; ni < 4; ni++) {
                    int kg = k0 + wnS + ni * 8 + 2 * tig;
                    float2 mv = *(const float2*)&mask[(size_t)q * SEQ + kg];
                    float s0 = acc[mi][ni][h * 2]     * 0.125f + mv.x * (-1e9f);
                    float s1 = acc[mi][ni][h * 2 + 1] * 0.125f + mv.y * (-1e9f);
                    acc[mi][ni][h * 2]     = s0;
                    acc[mi][ni][h * 2 + 1] = s1;
                    rm[mi * 2 + h] = fmaxf(rm[mi * 2 + h], fmaxf(s0, s1));
                }
            }
        }
#pragma unroll
        for (int j = 0; j < 4; j++) {
            rm[j] = fmaxf(rm[j], __shfl_xor_sync(0xffffffffu, rm[j], 1));
            rm[j] = fmaxf(rm[j], __shfl_xor_sync(0xffffffffu, rm[j], 2));
        }
        if (tig == 0) {
#pragma unroll
            for (int j = 0; j < 4; j++) {
                int r = wmS + (j >> 1) * 16 + gid + (j & 1) * 8;
                sm.part[r][wcol] = rm[j];
            }
        }
        __syncthreads();
        if (t < BQ) {
            float tm = fmaxf(sm.part[t][0], sm.part[t][1]);
            float mo = sm.row_m[t];
            float mn = fmaxf(mo, tm);
            sm.row_m[t] = mn;
            sm.row_scale[t] = __expf(mo - mn);
        }
        __syncthreads();

        float rs[4] = {0.f, 0.f, 0.f, 0.f};
#pragma unroll
        for (int mi = 0; mi < 2; mi++) {
#pragma unroll
            for (int h = 0; h < 2; h++) {
                int r = wmS + mi * 16 + gid + h * 8;
                float mrow = sm.row_m[r];
                float srow = 0.f;
#pragma unroll
                for (int ni = 0; ni < 4; ni++) {
                    srow += __expf(acc[mi][ni][h * 2]     - mrow);
                    srow += __expf(acc[mi][ni][h * 2 + 1] - mrow);
                }
                rs[mi * 2 + h] = srow;
            }
        }
#pragma unroll
        for (int j = 0; j < 4; j++) {
            rs[j] += __shfl_xor_sync(0xffffffffu, rs[j], 1);
            rs[j] += __shfl_xor_sync(0xffffffffu, rs[j], 2);
        }
        if (tig == 0) {
#pragma unroll
            for (int j = 0; j < 4; j++) {
                int r = wmS + (j >> 1) * 16 + gid + (j & 1) * 8;
                sm.part[r][wcol] = rs[j];
            }
        }
        __syncthreads();
        if (t < BQ)
            sm.row_l[t] = sm.row_l[t] * sm.row_scale[t] + sm.part[t][0] + sm.part[t][1];
        __syncthreads();
    }

    if (t < BQ) sm.row_inv[t] = 1.0f / sm.row_l[t];
    __syncthreads();

    // ------------------------- Pass B: write + PV -------------------------
    const int wmC = warp * 16;   // ctx warp layout: warp owns 16 q-rows x 64 d
    float cacc[8][4];
#pragma unroll
    for (int ni = 0; ni < 8; ni++)
#pragma unroll
        for (int r = 0; r < 4; r++) cacc[ni][r] = 0.f;

    for (int kb = 0; kb < NKB; kb++) {
        const int k0 = kb * KB;
#pragma unroll
        for (int i = 0; i < 4; i++) {
            int idx = t + i * 256;
            int r = idx >> 4;
            int c4 = (idx & 15) << 2;
            float4 a = *(const float4*)&Kb[(size_t)(k0 + r) * DEPTH + c4];
            *(uint4*)&sm.Ks[r][c4] = make_uint4(f2tf(a.x), f2tf(a.y), f2tf(a.z), f2tf(a.w));
            float4 b = *(const float4*)&Vb[(size_t)(k0 + r) * DEPTH + c4];
            sm.VTs[c4 + 0][r] = f2tf(b.x);
            sm.VTs[c4 + 1][r] = f2tf(b.y);
            sm.VTs[c4 + 2][r] = f2tf(b.z);
            sm.VTs[c4 + 3][r] = f2tf(b.w);
        }
        __syncthreads();

        float acc[2][4][4];
#pragma unroll
        for (int mi = 0; mi < 2; mi++)
#pragma unroll
            for (int ni = 0; ni < 4; ni++)
#pragma unroll
                for (int r = 0; r < 4; r++) acc[mi][ni][r] = 0.f;

#pragma unroll
        for (int kk = 0; kk < DEPTH; kk += 8) {
            unsigned af[2][4], bf[4][2];
#pragma unroll
            for (int mi = 0; mi < 2; mi++) {
                int r = wmS + mi * 16 + gid;
                af[mi][0] = sm.Qs[r][kk + tig];
                af[mi][1] = sm.Qs[r + 8][kk + tig];
                af[mi][2] = sm.Qs[r][kk + tig + 4];
                af[mi][3] = sm.Qs[r + 8][kk + tig + 4];
            }
#pragma unroll
            for (int ni = 0; ni < 4; ni++) {
                int c = wnS + ni * 8 + gid;
                bf[ni][0] = sm.Ks[c][kk + tig];
                bf[ni][1] = sm.Ks[c][kk + tig + 4];
            }
#pragma unroll
            for (int mi = 0; mi < 2; mi++)
#pragma unroll
                for (int ni = 0; ni < 4; ni++)
                    mma8(acc[mi][ni], af[mi], bf[ni]);
        }

        // p = exp(s - m) / l ; write attn ; stage tf32 P
#pragma unroll
        for (int mi = 0; mi < 2; mi++) {
#pragma unroll
            for (int h = 0; h < 2; h++) {
                int r = wmS + mi * 16 + gid + h * 8;
                int q = q0 + r;
                float mrow = sm.row_m[r];
                float inv  = sm.row_inv[r];
#pragma unroll
                for (int ni = 0; ni < 4; ni++) {
                    int c  = wnS + ni * 8 + 2 * tig;
                    int kg = k0 + c;
                    float2 mv = *(const float2*)&mask[(size_t)q * SEQ + kg];
                    float s0 = acc[mi][ni][h * 2]     * 0.125f + mv.x * (-1e9f);
                    float s1 = acc[mi][ni][h * 2 + 1] * 0.125f + mv.y * (-1e9f);
                    float p0 = __expf(s0 - mrow) * inv;
                    float p1 = __expf(s1 - mrow) * inv;
                    *(float2*)&attnb[(size_t)q * SEQ + kg] = make_float2(p0, p1);
                    uint2 pt = make_uint2(f2tf(p0), f2tf(p1));
                    *(uint2*)&sm.Ps[r][c] = pt;
                }
            }
        }
        __syncthreads();

        // ctx += P @ V  (K-dim = KB = 64)
#pragma unroll
        for (int kk = 0; kk < KB; kk += 8) {
            unsigned af[4], bf[8][2];
            int r = wmC + gid;
            af[0] = sm.Ps[r][kk + tig];
            af[1] = sm.Ps[r + 8][kk + tig];
            af[2] = sm.Ps[r][kk + tig + 4];
            af[3] = sm.Ps[r + 8][kk + tig + 4];
#pragma unroll
            for (int ni = 0; ni < 8; ni++) {
                int c = ni * 8 + gid;
                bf[ni][0] = sm.VTs[c][kk + tig];
                bf[ni][1] = sm.VTs[c][kk + tig + 4];
            }
#pragma unroll
            for (int ni = 0; ni < 8; ni++)
                mma8(cacc[ni], af, bf[ni]);
        }
        __syncthreads();
    }

    // write ctx (b, s, h*64 + d)
    const int b = bh >> 4;
    const int hh = bh & 15;
#pragma unroll
    for (int ni = 0; ni < 8; ni++) {
        int d0 = ni * 8 + 2 * tig;
        int q = q0 + wmC + gid;
        *(float2*)&ctx[((size_t)b * SEQ + q) * D_MODEL + hh * DEPTH + d0] =
            make_float2(cacc[ni][0], cacc[ni][1]);
        *(float2*)&ctx[((size_t)b * SEQ + q + 8) * D_MODEL + hh * DEPTH + d0] =
            make_float2(cacc[ni][2], cacc[ni][3]);
    }
}

// ---------------------------------------------------------------------------
// Inputs (metadata order): v, k, q, mask, wq_w, wq_b, wk_w, wk_b, wv_w, wv_b,
//                          dense_w, dense_b
// Output: [out (B*S*D_MODEL) | attn (B*H*S*S)] fp32
// ---------------------------------------------------------------------------
extern "C" void kernel_launch(void* const* d_in, const int* in_sizes, int n_in,
                              void* d_out, int out_size)
{
    const float* v_in = (const float*)d_in[0];
    const float* k_in = (const float*)d_in[1];
    const float* q_in = (const float*)d_in[2];
    const float* mask = (const float*)d_in[3];
    const float* wq_w = (const float*)d_in[4];
    const float* wq_b = (const float*)d_in[5];
    const float* wk_w = (const float*)d_in[6];
    const float* wk_b = (const float*)d_in[7];
    const float* wv_w = (const float*)d_in[8];
    const float* wv_b = (const float*)d_in[9];
    const float* dw   = (const float*)d_in[10];
    const float* db   = (const float*)d_in[11];

    float* out  = (float*)d_out;
    float* attn = out + (size_t)BATCH * SEQ * D_MODEL;

    float *gq, *gk, *gv, *gctx;
    cudaGetSymbolAddress((void**)&gq,   g_Q);
    cudaGetSymbolAddress((void**)&gk,   g_K);
    cudaGetSymbolAddress((void**)&gv,   g_V);
    cudaGetSymbolAddress((void**)&gctx, g_CTX);

    const int M = BATCH * SEQ;  // 8192

    dim3 gp(D_MODEL / 128, M / 128);     // (8, 64)
    gemm_tf32<1><<<gp, 256>>>(q_in, wq_w, wq_b, gq, M, D_MODEL, D_MODEL);
    gemm_tf32<1><<<gp, 256>>>(k_in, wk_w, wk_b, gk, M, D_MODEL, D_MODEL);
    gemm_tf32<1><<<gp, 256>>>(v_in, wv_w, wv_b, gv, M, D_MODEL, D_MODEL);

    static int smem_set = 0;
    size_t smem_bytes = sizeof(FusedSmem);
    cudaFuncSetAttribute(fused_attn, cudaFuncAttributeMaxDynamicSharedMemorySize,
                         (int)smem_bytes);
    (void)smem_set;

    dim3 gf(SEQ / BQ, BHN);              // (16, 64)
    fused_attn<<<gf, 256, smem_bytes>>>(gq, gk, gv, mask, attn, gctx);

    gemm_tf32<0><<<gp, 256>>>(gctx, dw, db, out, M, D_MODEL, D_MODEL);
}

// round 8
// speedup vs baseline: 2.3094x; 1.0944x over previous
#include <cuda_runtime.h>
#include <cstddef>

#define D_MODEL 1024
#define NUM_HEADS 16
#define DEPTH 64
#define BATCH 4
#define SEQ 2048
#define BHN (BATCH * NUM_HEADS)
#define BQ 128
#define KB 64
#define NKB (SEQ / KB)

// Scratch (device globals; no allocation allowed)
__device__ float g_Q[(size_t)BHN * SEQ * DEPTH];       // (b,h,s,d)
__device__ float g_K[(size_t)BHN * SEQ * DEPTH];
__device__ float g_V[(size_t)BHN * SEQ * DEPTH];
__device__ float g_CTX[(size_t)BATCH * SEQ * D_MODEL]; // (b,s,h*64+d)

// ---------------------------------------------------------------------------
// TF32 helpers
// ---------------------------------------------------------------------------
__device__ __forceinline__ unsigned f2tf(float x) {
    unsigned u;
    asm("cvt.rna.tf32.f32 %0, %1;" : "=r"(u) : "f"(x));
    return u;
}

// D += A(16x8) @ B(8x8)  (tf32, fp32 accum)
__device__ __forceinline__ void mma8(float* d, const unsigned* a, const unsigned* b) {
    asm volatile(
        "mma.sync.aligned.m16n8k8.row.col.f32.tf32.tf32.f32 "
        "{%0,%1,%2,%3}, {%4,%5,%6,%7}, {%8,%9}, {%0,%1,%2,%3};\n"
        : "+f"(d[0]), "+f"(d[1]), "+f"(d[2]), "+f"(d[3])
        : "r"(a[0]), "r"(a[1]), "r"(a[2]), "r"(a[3]), "r"(b[0]), "r"(b[1]));
}

__device__ __forceinline__ void store_hm(float* __restrict__ C, int m, int n, float v) {
    int b = m >> 11, s = m & (SEQ - 1);
    int h = n >> 6, d = n & (DEPTH - 1);
    C[(((size_t)(b * NUM_HEADS + h)) * SEQ + s) * DEPTH + d] = v;
}

// ---------------------------------------------------------------------------
// C = A(MxK) @ W(NxK)^T + bias   (tf32 tensor core)  -- projections + dense
// ---------------------------------------------------------------------------
template <int HEADMAJOR>
__global__ void __launch_bounds__(256, 2)
gemm_tf32(const float* __restrict__ A, const float* __restrict__ W,
          const float* __restrict__ bias, float* __restrict__ C,
          int M, int N, int K)
{
    const int BM = 128, BN = 128, BK = 32;
    __shared__ __align__(16) unsigned As[BM][BK + 4];
    __shared__ __align__(16) unsigned Bs[BN][BK + 4];

    const int m0 = blockIdx.y * BM;
    const int n0 = blockIdx.x * BN;
    const int t = threadIdx.x;
    const int warp = t >> 5, lane = t & 31;
    const int wm = (warp >> 2) * 64, wn = (warp & 3) * 32;
    const int gid = lane >> 2, tig = lane & 3;

    float acc[4][4][4];
#pragma unroll
    for (int mi = 0; mi < 4; mi++)
#pragma unroll
        for (int ni = 0; ni < 4; ni++)
#pragma unroll
            for (int r = 0; r < 4; r++) acc[mi][ni][r] = 0.f;

    for (int k0 = 0; k0 < K; k0 += BK) {
#pragma unroll
        for (int i = 0; i < 4; i++) {
            int idx = t + i * 256;
            int r = idx >> 3;
            int c4 = (idx & 7) << 2;
            float4 a = *(const float4*)&A[(size_t)(m0 + r) * K + k0 + c4];
            *(uint4*)&As[r][c4] = make_uint4(f2tf(a.x), f2tf(a.y), f2tf(a.z), f2tf(a.w));
            float4 b = *(const float4*)&W[(size_t)(n0 + r) * K + k0 + c4];
            *(uint4*)&Bs[r][c4] = make_uint4(f2tf(b.x), f2tf(b.y), f2tf(b.z), f2tf(b.w));
        }
        __syncthreads();

#pragma unroll
        for (int kk = 0; kk < BK; kk += 8) {
            unsigned af[4][4], bf[4][2];
#pragma unroll
            for (int mi = 0; mi < 4; mi++) {
                int r = wm + mi * 16 + gid;
                af[mi][0] = As[r][kk + tig];
                af[mi][1] = As[r + 8][kk + tig];
                af[mi][2] = As[r][kk + tig + 4];
                af[mi][3] = As[r + 8][kk + tig + 4];
            }
#pragma unroll
            for (int ni = 0; ni < 4; ni++) {
                int c = wn + ni * 8 + gid;
                bf[ni][0] = Bs[c][kk + tig];
                bf[ni][1] = Bs[c][kk + tig + 4];
            }
#pragma unroll
            for (int mi = 0; mi < 4; mi++)
#pragma unroll
                for (int ni = 0; ni < 4; ni++)
                    mma8(acc[mi][ni], af[mi], bf[ni]);
        }
        __syncthreads();
    }

#pragma unroll
    for (int mi = 0; mi < 4; mi++) {
        int r0 = m0 + wm + mi * 16 + gid;
#pragma unroll
        for (int ni = 0; ni < 4; ni++) {
            int c0 = n0 + wn + ni * 8 + 2 * tig;
            float b0 = bias[c0], b1 = bias[c0 + 1];
            if (HEADMAJOR) {
                store_hm(C, r0,     c0,     acc[mi][ni][0] + b0);
                store_hm(C, r0,     c0 + 1, acc[mi][ni][1] + b1);
                store_hm(C, r0 + 8, c0,     acc[mi][ni][2] + b0);
                store_hm(C, r0 + 8, c0 + 1, acc[mi][ni][3] + b1);
            } else {
                C[(size_t)r0 * N + c0]           = acc[mi][ni][0] + b0;
                C[(size_t)r0 * N + c0 + 1]       = acc[mi][ni][1] + b1;
                C[(size_t)(r0 + 8) * N + c0]     = acc[mi][ni][2] + b0;
                C[(size_t)(r0 + 8) * N + c0 + 1] = acc[mi][ni][3] + b1;
            }
        }
    }
}

// ---------------------------------------------------------------------------
// Fused attention: logits + softmax + attn-write + P@V per 128-row q-block.
// Pass A: online row max/sumexp (no gmem writes).
// Pass B: recompute S (bitwise identical), p = exp(s-m)/l, write attn once,
//         stage P in smem (tf32) and accumulate ctx += P@V on tensor cores.
// ---------------------------------------------------------------------------
struct __align__(16) FusedSmem {
    unsigned Qs[BQ][68];      // q rows x depth
    unsigned Ks[KB][68];      // k rows x depth
    unsigned VTs[DEPTH][68];  // depth x k (transposed)
    unsigned Ps[BQ][68];      // q rows x k (tf32 P for PV mma)
    float row_m[BQ];
    float row_l[BQ];
    float row_scale[BQ];
    float row_inv[BQ];
    float part[BQ][2];
};

__global__ void __launch_bounds__(256, 2)
fused_attn(const float* __restrict__ Q, const float* __restrict__ Kmat,
           const float* __restrict__ V, const float* __restrict__ mask,
           float* __restrict__ attn, float* __restrict__ ctx)
{
    extern __shared__ char smraw[];
    FusedSmem& sm = *(FusedSmem*)smraw;

    const int bh = blockIdx.y;
    const int q0 = blockIdx.x * BQ;
    const float* Qb = Q    + (size_t)bh * SEQ * DEPTH;
    const float* Kb = Kmat + (size_t)bh * SEQ * DEPTH;
    const float* Vb = V    + (size_t)bh * SEQ * DEPTH;
    float* attnb = attn + (size_t)bh * SEQ * SEQ;

    const int t = threadIdx.x;
    const int warp = t >> 5, lane = t & 31;
    const int gid = lane >> 2, tig = lane & 3;
    // S-tile warp layout: 4x2 warps, warp tile 32x32
    const int wmS = (warp >> 1) * 32;
    const int wnS = (warp & 1) * 32;
    const int wcol = warp & 1;

    if (t < BQ) { sm.row_m[t] = -1e30f; sm.row_l[t] = 0.f; }

    // Load Q tile (128 x 64) as tf32
#pragma unroll
    for (int i = 0; i < 8; i++) {
        int idx = t + i * 256;         // 0..2047
        int r = idx >> 4;              // 0..127
        int c4 = (idx & 15) << 2;      // 0..60
        float4 a = *(const float4*)&Qb[(size_t)(q0 + r) * DEPTH + c4];
        *(uint4*)&sm.Qs[r][c4] = make_uint4(f2tf(a.x), f2tf(a.y), f2tf(a.z), f2tf(a.w));
    }
    __syncthreads();

    // ------------------------- Pass A: stats -------------------------
    for (int kb = 0; kb < NKB; kb++) {
        const int k0 = kb * KB;
#pragma unroll
        for (int i = 0; i < 4; i++) {
            int idx = t + i * 256;     // 0..1023
            int r = idx >> 4;          // 0..63
            int c4 = (idx & 15) << 2;
            float4 a = *(const float4*)&Kb[(size_t)(k0 + r) * DEPTH + c4];
            *(uint4*)&sm.Ks[r][c4] = make_uint4(f2tf(a.x), f2tf(a.y), f2tf(a.z), f2tf(a.w));
        }
        __syncthreads();

        float acc[2][4][4];
#pragma unroll
        for (int mi = 0; mi < 2; mi++)
#pragma unroll
            for (int ni = 0; ni < 4; ni++)
#pragma unroll
                for (int r = 0; r < 4; r++) acc[mi][ni][r] = 0.f;

#pragma unroll
        for (int kk = 0; kk < DEPTH; kk += 8) {
            unsigned af[2][4], bf[4][2];
#pragma unroll
            for (int mi = 0; mi < 2; mi++) {
                int r = wmS + mi * 16 + gid;
                af[mi][0] = sm.Qs[r][kk + tig];
                af[mi][1] = sm.Qs[r + 8][kk + tig];
                af[mi][2] = sm.Qs[r][kk + tig + 4];
                af[mi][3] = sm.Qs[r + 8][kk + tig + 4];
            }
#pragma unroll
            for (int ni = 0; ni < 4; ni++) {
                int c = wnS + ni * 8 + gid;
                bf[ni][0] = sm.Ks[c][kk + tig];
                bf[ni][1] = sm.Ks[c][kk + tig + 4];
            }
#pragma unroll
            for (int mi = 0; mi < 2; mi++)
#pragma unroll
                for (int ni = 0; ni < 4; ni++)
                    mma8(acc[mi][ni], af[mi], bf[ni]);
        }

        // scale + mask in-place; per-thread row max
        float rm[4] = {-1e30f, -1e30f, -1e30f, -1e30f};
#pragma unroll
        for (int mi = 0; mi < 2; mi++) {
#pragma unroll
            for (int h = 0; h < 2; h++) {
                int r = wmS + mi * 16 + gid + h * 8;
                int q = q0 + r;
#pragma unroll
                for (int ni = 0; ni < 4; ni++) {
                    int kg = k0 + wnS + ni * 8 + 2 * tig;
                    float2 mv = *(const float2*)&mask[(size_t)q * SEQ + kg];
                    float s0 = acc[mi][ni][h * 2]     * 0.125f + mv.x * (-1e9f);
                    float s1 = acc[mi][ni][h * 2 + 1] * 0.125f + mv.y * (-1e9f);
                    acc[mi][ni][h * 2]     = s0;
                    acc[mi][ni][h * 2 + 1] = s1;
                    rm[mi * 2 + h] = fmaxf(rm[mi * 2 + h], fmaxf(s0, s1));
                }
            }
        }
#pragma unroll
        for (int j = 0; j < 4; j++) {
            rm[j] = fmaxf(rm[j], __shfl_xor_sync(0xffffffffu, rm[j], 1));
            rm[j] = fmaxf(rm[j], __shfl_xor_sync(0xffffffffu, rm[j], 2));
        }
        if (tig == 0) {
#pragma unroll
            for (int j = 0; j < 4; j++) {
                int r = wmS + (j >> 1) * 16 + gid + (j & 1) * 8;
                sm.part[r][wcol] = rm[j];
            }
        }
        __syncthreads();
        if (t < BQ) {
            float tm = fmaxf(sm.part[t][0], sm.part[t][1]);
            float mo = sm.row_m[t];
            float mn = fmaxf(mo, tm);
            sm.row_m[t] = mn;
            sm.row_scale[t] = __expf(mo - mn);
        }
        __syncthreads();

        float rs[4] = {0.f, 0.f, 0.f, 0.f};
#pragma unroll
        for (int mi = 0; mi < 2; mi++) {
#pragma unroll
            for (int h = 0; h < 2; h++) {
                int r = wmS + mi * 16 + gid + h * 8;
                float mrow = sm.row_m[r];
                float srow = 0.f;
#pragma unroll
                for (int ni = 0; ni < 4; ni++) {
                    srow += __expf(acc[mi][ni][h * 2]     - mrow);
                    srow += __expf(acc[mi][ni][h * 2 + 1] - mrow);
                }
                rs[mi * 2 + h] = srow;
            }
        }
#pragma unroll
        for (int j = 0; j < 4; j++) {
            rs[j] += __shfl_xor_sync(0xffffffffu, rs[j], 1);
            rs[j] += __shfl_xor_sync(0xffffffffu, rs[j], 2);
        }
        if (tig == 0) {
#pragma unroll
            for (int j = 0; j < 4; j++) {
                int r = wmS + (j >> 1) * 16 + gid + (j & 1) * 8;
                sm.part[r][wcol] = rs[j];
            }
        }
        __syncthreads();
        if (t < BQ)
            sm.row_l[t] = sm.row_l[t] * sm.row_scale[t] + sm.part[t][0] + sm.part[t][1];
        __syncthreads();
    }

    if (t < BQ) sm.row_inv[t] = 1.0f / sm.row_l[t];
    __syncthreads();

    // ------------------------- Pass B: write + PV -------------------------
    const int wmC = warp * 16;   // ctx warp layout: warp owns 16 q-rows x 64 d
    float cacc[8][4];
#pragma unroll
    for (int ni = 0; ni < 8; ni++)
#pragma unroll
        for (int r = 0; r < 4; r++) cacc[ni][r] = 0.f;

    for (int kb = 0; kb < NKB; kb++) {
        const int k0 = kb * KB;
#pragma unroll
        for (int i = 0; i < 4; i++) {
            int idx = t + i * 256;
            int r = idx >> 4;
            int c4 = (idx & 15) << 2;
            float4 a = *(const float4*)&Kb[(size_t)(k0 + r) * DEPTH + c4];
            *(uint4*)&sm.Ks[r][c4] = make_uint4(f2tf(a.x), f2tf(a.y), f2tf(a.z), f2tf(a.w));
            float4 b = *(const float4*)&Vb[(size_t)(k0 + r) * DEPTH + c4];
            sm.VTs[c4 + 0][r] = f2tf(b.x);
            sm.VTs[c4 + 1][r] = f2tf(b.y);
            sm.VTs[c4 + 2][r] = f2tf(b.z);
            sm.VTs[c4 + 3][r] = f2tf(b.w);
        }
        __syncthreads();

        float acc[2][4][4];
#pragma unroll
        for (int mi = 0; mi < 2; mi++)
#pragma unroll
            for (int ni = 0; ni < 4; ni++)
#pragma unroll
                for (int r = 0; r < 4; r++) acc[mi][ni][r] = 0.f;

#pragma unroll
        for (int kk = 0; kk < DEPTH; kk += 8) {
            unsigned af[2][4], bf[4][2];
#pragma unroll
            for (int mi = 0; mi < 2; mi++) {
                int r = wmS + mi * 16 + gid;
                af[mi][0] = sm.Qs[r][kk + tig];
                af[mi][1] = sm.Qs[r + 8][kk + tig];
                af[mi][2] = sm.Qs[r][kk + tig + 4];
                af[mi][3] = sm.Qs[r + 8][kk + tig + 4];
            }
#pragma unroll
            for (int ni = 0; ni < 4; ni++) {
                int c = wnS + ni * 8 + gid;
                bf[ni][0] = sm.Ks[c][kk + tig];
                bf[ni][1] = sm.Ks[c][kk + tig + 4];
            }
#pragma unroll
            for (int mi = 0; mi < 2; mi++)
#pragma unroll
                for (int ni = 0; ni < 4; ni++)
                    mma8(acc[mi][ni], af[mi], bf[ni]);
        }

        // p = exp(s - m) / l ; write attn ; stage tf32 P
#pragma unroll
        for (int mi = 0; mi < 2; mi++) {
#pragma unroll
            for (int h = 0; h < 2; h++) {
                int r = wmS + mi * 16 + gid + h * 8;
                int q = q0 + r;
                float mrow = sm.row_m[r];
                float inv  = sm.row_inv[r];
#pragma unroll
                for (int ni = 0; ni < 4; ni++) {
                    int c  = wnS + ni * 8 + 2 * tig;
                    int kg = k0 + c;
                    float2 mv = *(const float2*)&mask[(size_t)q * SEQ + kg];
                    float s0 = acc[mi][ni][h * 2]     * 0.125f + mv.x * (-1e9f);
                    float s1 = acc[mi][ni][h * 2 + 1] * 0.125f + mv.y * (-1e9f);
                    float p0 = __expf(s0 - mrow) * inv;
                    float p1 = __expf(s1 - mrow) * inv;
                    *(float2*)&attnb[(size_t)q * SEQ + kg] = make_float2(p0, p1);
                    uint2 pt = make_uint2(f2tf(p0), f2tf(p1));
                    *(uint2*)&sm.Ps[r][c] = pt;
                }
            }
        }
        __syncthreads();

        // ctx += P @ V  (K-dim = KB = 64)
#pragma unroll
        for (int kk = 0; kk < KB; kk += 8) {
            unsigned af[4], bf[8][2];
            int r = wmC + gid;
            af[0] = sm.Ps[r][kk + tig];
            af[1] = sm.Ps[r + 8][kk + tig];
            af[2] = sm.Ps[r][kk + tig + 4];
            af[3] = sm.Ps[r + 8][kk + tig + 4];
#pragma unroll
            for (int ni = 0; ni < 8; ni++) {
                int c = ni * 8 + gid;
                bf[ni][0] = sm.VTs[c][kk + tig];
                bf[ni][1] = sm.VTs[c][kk + tig + 4];
            }
#pragma unroll
            for (int ni = 0; ni < 8; ni++)
                mma8(cacc[ni], af, bf[ni]);
        }
        __syncthreads();
    }

    // write ctx (b, s, h*64 + d)
    const int b = bh >> 4;
    const int hh = bh & 15;
#pragma unroll
    for (int ni = 0; ni < 8; ni++) {
        int d0 = ni * 8 + 2 * tig;
        int q = q0 + wmC + gid;
        *(float2*)&ctx[((size_t)b * SEQ + q) * D_MODEL + hh * DEPTH + d0] =
            make_float2(cacc[ni][0], cacc[ni][1]);
        *(float2*)&ctx[((size_t)b * SEQ + q + 8) * D_MODEL + hh * DEPTH + d0] =
            make_float2(cacc[ni][2], cacc[ni][3]);
    }
}

// ---------------------------------------------------------------------------
// Inputs (metadata order): v, k, q, mask, wq_w, wq_b, wk_w, wk_b, wv_w, wv_b,
//                          dense_w, dense_b
// Output: [out (B*S*D_MODEL) | attn (B*H*S*S)] fp32
// ---------------------------------------------------------------------------
extern "C" void kernel_launch(void* const* d_in, const int* in_sizes, int n_in,
                              void* d_out, int out_size)
{
    const float* v_in = (const float*)d_in[0];
    const float* k_in = (const float*)d_in[1];
    const float* q_in = (const float*)d_in[2];
    const float* mask = (const float*)d_in[3];
    const float* wq_w = (const float*)d_in[4];
    const float* wq_b = (const float*)d_in[5];
    const float* wk_w = (const float*)d_in[6];
    const float* wk_b = (const float*)d_in[7];
    const float* wv_w = (const float*)d_in[8];
    const float* wv_b = (const float*)d_in[9];
    const float* dw   = (const float*)d_in[10];
    const float* db   = (const float*)d_in[11];

    float* out  = (float*)d_out;
    float* attn = out + (size_t)BATCH * SEQ * D_MODEL;

    float *gq, *gk, *gv, *gctx;
    cudaGetSymbolAddress((void**)&gq,   g_Q);
    cudaGetSymbolAddress((void**)&gk,   g_K);
    cudaGetSymbolAddress((void**)&gv,   g_V);
    cudaGetSymbolAddress((void**)&gctx, g_CTX);

    const int M = BATCH * SEQ;  // 8192

    dim3 gp(D_MODEL / 128, M / 128);     // (8, 64)
    gemm_tf32<1><<<gp, 256>>>(q_in, wq_w, wq_b, gq, M, D_MODEL, D_MODEL);
    gemm_tf32<1><<<gp, 256>>>(k_in, wk_w, wk_b, gk, M, D_MODEL, D_MODEL);
    gemm_tf32<1><<<gp, 256>>>(v_in, wv_w, wv_b, gv, M, D_MODEL, D_MODEL);

    size_t smem_bytes = sizeof(FusedSmem);
    cudaFuncSetAttribute(fused_attn, cudaFuncAttributeMaxDynamicSharedMemorySize,
                         (int)smem_bytes);

    dim3 gf(SEQ / BQ, BHN);              // (16, 64)
    fused_attn<<<gf, 256, smem_bytes>>>(gq, gk, gv, mask, attn, gctx);

    gemm_tf32<0><<<gp, 256>>>(gctx, dw, db, out, M, D_MODEL, D_MODEL);
}

// round 9
// speedup vs baseline: 3.0513x; 1.3213x over previous
#include <cuda_runtime.h>
#include <cuda_fp16.h>
#include <cstddef>

#define D_MODEL 1024
#define NUM_HEADS 16
#define DEPTH 64
#define BATCH 4
#define SEQ 2048
#define BHN (BATCH * NUM_HEADS)
#define BQ 128
#define KB 64
#define NKB (SEQ / KB)

// Scratch (device globals; no allocation allowed)
__device__ float g_Q[(size_t)BHN * SEQ * DEPTH];       // (b,h,s,d)
__device__ float g_K[(size_t)BHN * SEQ * DEPTH];
__device__ float g_V[(size_t)BHN * SEQ * DEPTH];
__device__ float g_CTX[(size_t)BATCH * SEQ * D_MODEL]; // (b,s,h*64+d)

// ---------------------------------------------------------------------------
// FP16 helpers
// ---------------------------------------------------------------------------
__device__ __forceinline__ unsigned pack2(float a, float b) {
    __half2 h = __floats2half2_rn(a, b);
    return *(unsigned*)&h;
}

// D(16x8) += A(16x16) @ B(16x8)   fp16 inputs, fp32 accum
__device__ __forceinline__ void mma16(float* d, const unsigned* a, const unsigned* b) {
    asm volatile(
        "mma.sync.aligned.m16n8k16.row.col.f32.f16.f16.f32 "
        "{%0,%1,%2,%3}, {%4,%5,%6,%7}, {%8,%9}, {%0,%1,%2,%3};\n"
        : "+f"(d[0]), "+f"(d[1]), "+f"(d[2]), "+f"(d[3])
        : "r"(a[0]), "r"(a[1]), "r"(a[2]), "r"(a[3]), "r"(b[0]), "r"(b[1]));
}

__device__ __forceinline__ void store_hm(float* __restrict__ C, int m, int n, float v) {
    int b = m >> 11, s = m & (SEQ - 1);
    int h = n >> 6, d = n & (DEPTH - 1);
    C[(((size_t)(b * NUM_HEADS + h)) * SEQ + s) * DEPTH + d] = v;
}

// ---------------------------------------------------------------------------
// C = A(MxK) @ W(NxK)^T + bias   (fp16 tensor core, fp32 accum)
// Tile 128x128, BK=32, 8 warps (2x4), warp tile 64x32.
// ---------------------------------------------------------------------------
#define GSTR 40   // half stride of gemm smem rows (BK=32 + 8 pad)

template <int HEADMAJOR>
__global__ void __launch_bounds__(256, 2)
gemm_f16(const float* __restrict__ A, const float* __restrict__ W,
         const float* __restrict__ bias, float* __restrict__ C,
         int M, int N, int K)
{
    const int BM = 128, BN = 128, BK = 32;
    __shared__ __align__(16) __half As[BM][GSTR];
    __shared__ __align__(16) __half Bs[BN][GSTR];

    const int m0 = blockIdx.y * BM;
    const int n0 = blockIdx.x * BN;
    const int t = threadIdx.x;
    const int warp = t >> 5, lane = t & 31;
    const int wm = (warp >> 2) * 64, wn = (warp & 3) * 32;
    const int gid = lane >> 2, tig = lane & 3;

    float acc[4][4][4];
#pragma unroll
    for (int mi = 0; mi < 4; mi++)
#pragma unroll
        for (int ni = 0; ni < 4; ni++)
#pragma unroll
            for (int r = 0; r < 4; r++) acc[mi][ni][r] = 0.f;

    for (int k0 = 0; k0 < K; k0 += BK) {
#pragma unroll
        for (int i = 0; i < 4; i++) {
            int idx = t + i * 256;              // 0..1023
            int r = idx >> 3;                   // 0..127
            int c4 = (idx & 7) << 2;            // 0,4,..,28 (half index)
            float4 a = *(const float4*)&A[(size_t)(m0 + r) * K + k0 + c4];
            *(uint2*)&As[r][c4] = make_uint2(pack2(a.x, a.y), pack2(a.z, a.w));
            float4 b = *(const float4*)&W[(size_t)(n0 + r) * K + k0 + c4];
            *(uint2*)&Bs[r][c4] = make_uint2(pack2(b.x, b.y), pack2(b.z, b.w));
        }
        __syncthreads();

#pragma unroll
        for (int ks = 0; ks < BK; ks += 16) {
            unsigned af[4][4], bf[4][2];
#pragma unroll
            for (int mi = 0; mi < 4; mi++) {
                int r = wm + mi * 16 + gid;
                af[mi][0] = *(const unsigned*)&As[r][ks + 2 * tig];
                af[mi][1] = *(const unsigned*)&As[r + 8][ks + 2 * tig];
                af[mi][2] = *(const unsigned*)&As[r][ks + 8 + 2 * tig];
                af[mi][3] = *(const unsigned*)&As[r + 8][ks + 8 + 2 * tig];
            }
#pragma unroll
            for (int ni = 0; ni < 4; ni++) {
                int c = wn + ni * 8 + gid;
                bf[ni][0] = *(const unsigned*)&Bs[c][ks + 2 * tig];
                bf[ni][1] = *(const unsigned*)&Bs[c][ks + 8 + 2 * tig];
            }
#pragma unroll
            for (int mi = 0; mi < 4; mi++)
#pragma unroll
                for (int ni = 0; ni < 4; ni++)
                    mma16(acc[mi][ni], af[mi], bf[ni]);
        }
        __syncthreads();
    }

#pragma unroll
    for (int mi = 0; mi < 4; mi++) {
        int r0 = m0 + wm + mi * 16 + gid;
#pragma unroll
        for (int ni = 0; ni < 4; ni++) {
            int c0 = n0 + wn + ni * 8 + 2 * tig;
            float b0 = bias[c0], b1 = bias[c0 + 1];
            if (HEADMAJOR) {
                store_hm(C, r0,     c0,     acc[mi][ni][0] + b0);
                store_hm(C, r0,     c0 + 1, acc[mi][ni][1] + b1);
                store_hm(C, r0 + 8, c0,     acc[mi][ni][2] + b0);
                store_hm(C, r0 + 8, c0 + 1, acc[mi][ni][3] + b1);
            } else {
                C[(size_t)r0 * N + c0]           = acc[mi][ni][0] + b0;
                C[(size_t)r0 * N + c0 + 1]       = acc[mi][ni][1] + b1;
                C[(size_t)(r0 + 8) * N + c0]     = acc[mi][ni][2] + b0;
                C[(size_t)(r0 + 8) * N + c0 + 1] = acc[mi][ni][3] + b1;
            }
        }
    }
}

// ---------------------------------------------------------------------------
// Fused attention (fp16 mma): logits + softmax + attn-write + P@V.
// Pass A: online row max/sumexp. Pass B: recompute S, write attn once,
// stage P (half) in smem, ctx += P@V.
// ---------------------------------------------------------------------------
#define QSTR 72   // half stride for [row][64] tiles (+8 pad)
#define VSTR 68   // half stride for V^T tile

struct __align__(16) FusedSmem {
    __half Qs[BQ][QSTR];      // q rows x depth
    __half Ks[KB][QSTR];      // k rows x depth
    __half Vt[DEPTH][VSTR];   // depth x k (transposed, half2-packed k pairs)
    __half Ps[BQ][QSTR];      // q rows x k (P for PV mma)
    float row_m[BQ];
    float row_l[BQ];
    float row_scale[BQ];
    float row_inv[BQ];
    float part[BQ][2];
};

__global__ void __launch_bounds__(256, 2)
fused_attn(const float* __restrict__ Q, const float* __restrict__ Kmat,
           const float* __restrict__ V, const float* __restrict__ mask,
           float* __restrict__ attn, float* __restrict__ ctx)
{
    extern __shared__ char smraw[];
    FusedSmem& sm = *(FusedSmem*)smraw;

    const int bh = blockIdx.y;
    const int q0 = blockIdx.x * BQ;
    const float* Qb = Q    + (size_t)bh * SEQ * DEPTH;
    const float* Kb = Kmat + (size_t)bh * SEQ * DEPTH;
    const float* Vb = V    + (size_t)bh * SEQ * DEPTH;
    float* attnb = attn + (size_t)bh * SEQ * SEQ;

    const int t = threadIdx.x;
    const int warp = t >> 5, lane = t & 31;
    const int gid = lane >> 2, tig = lane & 3;
    // S-tile warp layout: 4x2 warps, warp tile 32x32
    const int wmS = (warp >> 1) * 32;
    const int wnS = (warp & 1) * 32;
    const int wcol = warp & 1;

    if (t < BQ) { sm.row_m[t] = -1e30f; sm.row_l[t] = 0.f; }

    // Load Q tile (128 x 64) -> fp16
#pragma unroll
    for (int i = 0; i < 8; i++) {
        int idx = t + i * 256;         // 0..2047
        int r = idx >> 4;              // 0..127
        int c4 = (idx & 15) << 2;      // 0..60
        float4 a = *(const float4*)&Qb[(size_t)(q0 + r) * DEPTH + c4];
        *(uint2*)&sm.Qs[r][c4] = make_uint2(pack2(a.x, a.y), pack2(a.z, a.w));
    }
    __syncthreads();

    // ------------------------- Pass A: stats -------------------------
    for (int kb = 0; kb < NKB; kb++) {
        const int k0 = kb * KB;
#pragma unroll
        for (int i = 0; i < 4; i++) {
            int idx = t + i * 256;     // 0..1023
            int r = idx >> 4;          // 0..63
            int c4 = (idx & 15) << 2;
            float4 a = *(const float4*)&Kb[(size_t)(k0 + r) * DEPTH + c4];
            *(uint2*)&sm.Ks[r][c4] = make_uint2(pack2(a.x, a.y), pack2(a.z, a.w));
        }
        __syncthreads();

        float acc[2][4][4];
#pragma unroll
        for (int mi = 0; mi < 2; mi++)
#pragma unroll
            for (int ni = 0; ni < 4; ni++)
#pragma unroll
                for (int r = 0; r < 4; r++) acc[mi][ni][r] = 0.f;

#pragma unroll
        for (int ks = 0; ks < DEPTH; ks += 16) {
            unsigned af[2][4], bf[4][2];
#pragma unroll
            for (int mi = 0; mi < 2; mi++) {
                int r = wmS + mi * 16 + gid;
                af[mi][0] = *(const unsigned*)&sm.Qs[r][ks + 2 * tig];
                af[mi][1] = *(const unsigned*)&sm.Qs[r + 8][ks + 2 * tig];
                af[mi][2] = *(const unsigned*)&sm.Qs[r][ks + 8 + 2 * tig];
                af[mi][3] = *(const unsigned*)&sm.Qs[r + 8][ks + 8 + 2 * tig];
            }
#pragma unroll
            for (int ni = 0; ni < 4; ni++) {
                int c = wnS + ni * 8 + gid;
                bf[ni][0] = *(const unsigned*)&sm.Ks[c][ks + 2 * tig];
                bf[ni][1] = *(const unsigned*)&sm.Ks[c][ks + 8 + 2 * tig];
            }
#pragma unroll
            for (int mi = 0; mi < 2; mi++)
#pragma unroll
                for (int ni = 0; ni < 4; ni++)
                    mma16(acc[mi][ni], af[mi], bf[ni]);
        }

        // scale + mask in-place; per-thread row max
        float rm[4] = {-1e30f, -1e30f, -1e30f, -1e30f};
#pragma unroll
        for (int mi = 0; mi < 2; mi++) {
#pragma unroll
            for (int h = 0; h < 2; h++) {
                int r = wmS + mi * 16 + gid + h * 8;
                int q = q0 + r;
#pragma unroll
                for (int ni = 0; ni < 4; ni++) {
                    int kg = k0 + wnS + ni * 8 + 2 * tig;
                    float2 mv = *(const float2*)&mask[(size_t)q * SEQ + kg];
                    float s0 = acc[mi][ni][h * 2]     * 0.125f + mv.x * (-1e9f);
                    float s1 = acc[mi][ni][h * 2 + 1] * 0.125f + mv.y * (-1e9f);
                    acc[mi][ni][h * 2]     = s0;
                    acc[mi][ni][h * 2 + 1] = s1;
                    rm[mi * 2 + h] = fmaxf(rm[mi * 2 + h], fmaxf(s0, s1));
                }
            }
        }
#pragma unroll
        for (int j = 0; j < 4; j++) {
            rm[j] = fmaxf(rm[j], __shfl_xor_sync(0xffffffffu, rm[j], 1));
            rm[j] = fmaxf(rm[j], __shfl_xor_sync(0xffffffffu, rm[j], 2));
        }
        if (tig == 0) {
#pragma unroll
            for (int j = 0; j < 4; j++) {
                int r = wmS + (j >> 1) * 16 + gid + (j & 1) * 8;
                sm.part[r][wcol] = rm[j];
            }
        }
        __syncthreads();
        if (t < BQ) {
            float tm = fmaxf(sm.part[t][0], sm.part[t][1]);
            float mo = sm.row_m[t];
            float mn = fmaxf(mo, tm);
            sm.row_m[t] = mn;
            sm.row_scale[t] = __expf(mo - mn);
        }
        __syncthreads();

        float rs[4] = {0.f, 0.f, 0.f, 0.f};
#pragma unroll
        for (int mi = 0; mi < 2; mi++) {
#pragma unroll
            for (int h = 0; h < 2; h++) {
                int r = wmS + mi * 16 + gid + h * 8;
                float mrow = sm.row_m[r];
                float srow = 0.f;
#pragma unroll
                for (int ni = 0; ni < 4; ni++) {
                    srow += __expf(acc[mi][ni][h * 2]     - mrow);
                    srow += __expf(acc[mi][ni][h * 2 + 1] - mrow);
                }
                rs[mi * 2 + h] = srow;
            }
        }
#pragma unroll
        for (int j = 0; j < 4; j++) {
            rs[j] += __shfl_xor_sync(0xffffffffu, rs[j], 1);
            rs[j] += __shfl_xor_sync(0xffffffffu, rs[j], 2);
        }
        if (tig == 0) {
#pragma unroll
            for (int j = 0; j < 4; j++) {
                int r = wmS + (j >> 1) * 16 + gid + (j & 1) * 8;
                sm.part[r][wcol] = rs[j];
            }
        }
        __syncthreads();
        if (t < BQ)
            sm.row_l[t] = sm.row_l[t] * sm.row_scale[t] + sm.part[t][0] + sm.part[t][1];
        __syncthreads();
    }

    if (t < BQ) sm.row_inv[t] = 1.0f / sm.row_l[t];
    __syncthreads();

    // ------------------------- Pass B: write + PV -------------------------
    const int wmC = warp * 16;   // ctx warp layout: warp owns 16 q-rows x 64 d
    float cacc[8][4];
#pragma unroll
    for (int ni = 0; ni < 8; ni++)
#pragma unroll
        for (int r = 0; r < 4; r++) cacc[ni][r] = 0.f;

    for (int kb = 0; kb < NKB; kb++) {
        const int k0 = kb * KB;
        // K tile (fp16)
#pragma unroll
        for (int i = 0; i < 4; i++) {
            int idx = t + i * 256;
            int r = idx >> 4;
            int c4 = (idx & 15) << 2;
            float4 a = *(const float4*)&Kb[(size_t)(k0 + r) * DEPTH + c4];
            *(uint2*)&sm.Ks[r][c4] = make_uint2(pack2(a.x, a.y), pack2(a.z, a.w));
        }
        // V^T tile: 2x2 micro-transpose, half2-packed along k
#pragma unroll
        for (int i = 0; i < 4; i++) {
            int blk = t + i * 256;           // 0..1023
            int k2 = blk >> 5;               // 0..31
            int d2 = blk & 31;               // 0..31
            int k = 2 * k2, d = 2 * d2;
            float2 va = *(const float2*)&Vb[(size_t)(k0 + k) * DEPTH + d];
            float2 vb2 = *(const float2*)&Vb[(size_t)(k0 + k + 1) * DEPTH + d];
            *(unsigned*)&sm.Vt[d][2 * k2]     = pack2(va.x, vb2.x);
            *(unsigned*)&sm.Vt[d + 1][2 * k2] = pack2(va.y, vb2.y);
        }
        __syncthreads();

        float acc[2][4][4];
#pragma unroll
        for (int mi = 0; mi < 2; mi++)
#pragma unroll
            for (int ni = 0; ni < 4; ni++)
#pragma unroll
                for (int r = 0; r < 4; r++) acc[mi][ni][r] = 0.f;

#pragma unroll
        for (int ks = 0; ks < DEPTH; ks += 16) {
            unsigned af[2][4], bf[4][2];
#pragma unroll
            for (int mi = 0; mi < 2; mi++) {
                int r = wmS + mi * 16 + gid;
                af[mi][0] = *(const unsigned*)&sm.Qs[r][ks + 2 * tig];
                af[mi][1] = *(const unsigned*)&sm.Qs[r + 8][ks + 2 * tig];
                af[mi][2] = *(const unsigned*)&sm.Qs[r][ks + 8 + 2 * tig];
                af[mi][3] = *(const unsigned*)&sm.Qs[r + 8][ks + 8 + 2 * tig];
            }
#pragma unroll
            for (int ni = 0; ni < 4; ni++) {
                int c = wnS + ni * 8 + gid;
                bf[ni][0] = *(const unsigned*)&sm.Ks[c][ks + 2 * tig];
                bf[ni][1] = *(const unsigned*)&sm.Ks[c][ks + 8 + 2 * tig];
            }
#pragma unroll
            for (int mi = 0; mi < 2; mi++)
#pragma unroll
                for (int ni = 0; ni < 4; ni++)
                    mma16(acc[mi][ni], af[mi], bf[ni]);
        }

        // p = exp(s - m) / l ; write attn ; stage half P
#pragma unroll
        for (int mi = 0; mi < 2; mi++) {
#pragma unroll
            for (int h = 0; h < 2; h++) {
                int r = wmS + mi * 16 + gid + h * 8;
                int q = q0 + r;
                float mrow = sm.row_m[r];
                float inv  = sm.row_inv[r];
#pragma unroll
                for (int ni = 0; ni < 4; ni++) {
                    int c  = wnS + ni * 8 + 2 * tig;
                    int kg = k0 + c;
                    float2 mv = *(const float2*)&mask[(size_t)q * SEQ + kg];
                    float s0 = acc[mi][ni][h * 2]     * 0.125f + mv.x * (-1e9f);
                    float s1 = acc[mi][ni][h * 2 + 1] * 0.125f + mv.y * (-1e9f);
                    float p0 = __expf(s0 - mrow) * inv;
                    float p1 = __expf(s1 - mrow) * inv;
                    *(float2*)&attnb[(size_t)q * SEQ + kg] = make_float2(p0, p1);
                    *(unsigned*)&sm.Ps[r][c] = pack2(p0, p1);
                }
            }
        }
        __syncthreads();

        // ctx += P @ V  (K-dim = KB = 64)
#pragma unroll
        for (int ks = 0; ks < KB; ks += 16) {
            unsigned af[4], bf[8][2];
            int r = wmC + gid;
            af[0] = *(const unsigned*)&sm.Ps[r][ks + 2 * tig];
            af[1] = *(const unsigned*)&sm.Ps[r + 8][ks + 2 * tig];
            af[2] = *(const unsigned*)&sm.Ps[r][ks + 8 + 2 * tig];
            af[3] = *(const unsigned*)&sm.Ps[r + 8][ks + 8 + 2 * tig];
#pragma unroll
            for (int ni = 0; ni < 8; ni++) {
                int c = ni * 8 + gid;
                bf[ni][0] = *(const unsigned*)&sm.Vt[c][ks + 2 * tig];
                bf[ni][1] = *(const unsigned*)&sm.Vt[c][ks + 8 + 2 * tig];
            }
#pragma unroll
            for (int ni = 0; ni < 8; ni++)
                mma16(cacc[ni], af, bf[ni]);
        }
        __syncthreads();
    }

    // write ctx (b, s, h*64 + d)
    const int b = bh >> 4;
    const int hh = bh & 15;
#pragma unroll
    for (int ni = 0; ni < 8; ni++) {
        int d0 = ni * 8 + 2 * tig;
        int q = q0 + wmC + gid;
        *(float2*)&ctx[((size_t)b * SEQ + q) * D_MODEL + hh * DEPTH + d0] =
            make_float2(cacc[ni][0], cacc[ni][1]);
        *(float2*)&ctx[((size_t)b * SEQ + q + 8) * D_MODEL + hh * DEPTH + d0] =
            make_float2(cacc[ni][2], cacc[ni][3]);
    }
}

// ---------------------------------------------------------------------------
// Inputs (metadata order): v, k, q, mask, wq_w, wq_b, wk_w, wk_b, wv_w, wv_b,
//                          dense_w, dense_b
// Output: [out (B*S*D_MODEL) | attn (B*H*S*S)] fp32
// ---------------------------------------------------------------------------
extern "C" void kernel_launch(void* const* d_in, const int* in_sizes, int n_in,
                              void* d_out, int out_size)
{
    const float* v_in = (const float*)d_in[0];
    const float* k_in = (const float*)d_in[1];
    const float* q_in = (const float*)d_in[2];
    const float* mask = (const float*)d_in[3];
    const float* wq_w = (const float*)d_in[4];
    const float* wq_b = (const float*)d_in[5];
    const float* wk_w = (const float*)d_in[6];
    const float* wk_b = (const float*)d_in[7];
    const float* wv_w = (const float*)d_in[8];
    const float* wv_b = (const float*)d_in[9];
    const float* dw   = (const float*)d_in[10];
    const float* db   = (const float*)d_in[11];

    float* out  = (float*)d_out;
    float* attn = out + (size_t)BATCH * SEQ * D_MODEL;

    float *gq, *gk, *gv, *gctx;
    cudaGetSymbolAddress((void**)&gq,   g_Q);
    cudaGetSymbolAddress((void**)&gk,   g_K);
    cudaGetSymbolAddress((void**)&gv,   g_V);
    cudaGetSymbolAddress((void**)&gctx, g_CTX);

    const int M = BATCH * SEQ;  // 8192

    dim3 gp(D_MODEL / 128, M / 128);     // (8, 64)
    gemm_f16<1><<<gp, 256>>>(q_in, wq_w, wq_b, gq, M, D_MODEL, D_MODEL);
    gemm_f16<1><<<gp, 256>>>(k_in, wk_w, wk_b, gk, M, D_MODEL, D_MODEL);
    gemm_f16<1><<<gp, 256>>>(v_in, wv_w, wv_b, gv, M, D_MODEL, D_MODEL);

    size_t smem_bytes = sizeof(FusedSmem);
    cudaFuncSetAttribute(fused_attn, cudaFuncAttributeMaxDynamicSharedMemorySize,
                         (int)smem_bytes);

    dim3 gf(SEQ / BQ, BHN);              // (16, 64)
    fused_attn<<<gf, 256, smem_bytes>>>(gq, gk, gv, mask, attn, gctx);

    gemm_f16<0><<<gp, 256>>>(gctx, dw, db, out, M, D_MODEL, D_MODEL);
}

// round 10
// speedup vs baseline: 3.5725x; 1.1708x over previous
#include <cuda_runtime.h>
#include <cuda_fp16.h>
#include <cstddef>

#define D_MODEL 1024
#define NUM_HEADS 16
#define DEPTH 64
#define BATCH 4
#define SEQ 2048
#define BHN (BATCH * NUM_HEADS)
#define BQ 128
#define KB 64
#define NKB (SEQ / KB)
#define QSTR 72   // half stride (64 + 8 pad) -> conflict-free ldmatrix rows

// Scratch (device globals; no allocation allowed)
__device__ float g_Q[(size_t)BHN * SEQ * DEPTH];       // (b,h,s,d)
__device__ float g_K[(size_t)BHN * SEQ * DEPTH];
__device__ float g_V[(size_t)BHN * SEQ * DEPTH];
__device__ float g_CTX[(size_t)BATCH * SEQ * D_MODEL]; // (b,s,h*64+d)

// ---------------------------------------------------------------------------
// FP16 helpers
// ---------------------------------------------------------------------------
__device__ __forceinline__ unsigned pack2(float a, float b) {
    __half2 h = __floats2half2_rn(a, b);
    return *(unsigned*)&h;
}

// D(16x8) += A(16x16) @ B(16x8)   fp16 inputs, fp32 accum
__device__ __forceinline__ void mma16(float* d, const unsigned* a, const unsigned* b) {
    asm volatile(
        "mma.sync.aligned.m16n8k16.row.col.f32.f16.f16.f32 "
        "{%0,%1,%2,%3}, {%4,%5,%6,%7}, {%8,%9}, {%0,%1,%2,%3};\n"
        : "+f"(d[0]), "+f"(d[1]), "+f"(d[2]), "+f"(d[3])
        : "r"(a[0]), "r"(a[1]), "r"(a[2]), "r"(a[3]), "r"(b[0]), "r"(b[1]));
}

__device__ __forceinline__ void ldsm_x4(unsigned& r0, unsigned& r1,
                                        unsigned& r2, unsigned& r3, unsigned addr) {
    asm volatile("ldmatrix.sync.aligned.m8n8.x4.shared.b16 {%0,%1,%2,%3}, [%4];"
                 : "=r"(r0), "=r"(r1), "=r"(r2), "=r"(r3) : "r"(addr));
}
__device__ __forceinline__ void ldsm_x4_t(unsigned& r0, unsigned& r1,
                                          unsigned& r2, unsigned& r3, unsigned addr) {
    asm volatile("ldmatrix.sync.aligned.m8n8.x4.trans.shared.b16 {%0,%1,%2,%3}, [%4];"
                 : "=r"(r0), "=r"(r1), "=r"(r2), "=r"(r3) : "r"(addr));
}

__device__ __forceinline__ void store_hm(float* __restrict__ C, int m, int n, float v) {
    int b = m >> 11, s = m & (SEQ - 1);
    int h = n >> 6, d = n & (DEPTH - 1);
    C[(((size_t)(b * NUM_HEADS + h)) * SEQ + s) * DEPTH + d] = v;
}

// ---------------------------------------------------------------------------
// C = A(MxK) @ W(NxK)^T + bias   (fp16 tensor core, fp32 accum)
// Tile 128x128, BK=32, 8 warps (2x4), warp tile 64x32.
// ---------------------------------------------------------------------------
#define GSTR 40   // half stride of gemm smem rows (BK=32 + 8 pad)

template <int HEADMAJOR>
__global__ void __launch_bounds__(256, 2)
gemm_f16(const float* __restrict__ A, const float* __restrict__ W,
         const float* __restrict__ bias, float* __restrict__ C,
         int M, int N, int K)
{
    const int BM = 128, BN = 128, BK = 32;
    __shared__ __align__(16) __half As[BM][GSTR];
    __shared__ __align__(16) __half Bs[BN][GSTR];

    const int m0 = blockIdx.y * BM;
    const int n0 = blockIdx.x * BN;
    const int t = threadIdx.x;
    const int warp = t >> 5, lane = t & 31;
    const int wm = (warp >> 2) * 64, wn = (warp & 3) * 32;
    const int gid = lane >> 2, tig = lane & 3;

    float acc[4][4][4];
#pragma unroll
    for (int mi = 0; mi < 4; mi++)
#pragma unroll
        for (int ni = 0; ni < 4; ni++)
#pragma unroll
            for (int r = 0; r < 4; r++) acc[mi][ni][r] = 0.f;

    for (int k0 = 0; k0 < K; k0 += BK) {
#pragma unroll
        for (int i = 0; i < 4; i++) {
            int idx = t + i * 256;              // 0..1023
            int r = idx >> 3;                   // 0..127
            int c4 = (idx & 7) << 2;            // half index
            float4 a = *(const float4*)&A[(size_t)(m0 + r) * K + k0 + c4];
            *(uint2*)&As[r][c4] = make_uint2(pack2(a.x, a.y), pack2(a.z, a.w));
            float4 b = *(const float4*)&W[(size_t)(n0 + r) * K + k0 + c4];
            *(uint2*)&Bs[r][c4] = make_uint2(pack2(b.x, b.y), pack2(b.z, b.w));
        }
        __syncthreads();

#pragma unroll
        for (int ks = 0; ks < BK; ks += 16) {
            unsigned af[4][4], bf[4][2];
#pragma unroll
            for (int mi = 0; mi < 4; mi++) {
                int r = wm + mi * 16 + gid;
                af[mi][0] = *(const unsigned*)&As[r][ks + 2 * tig];
                af[mi][1] = *(const unsigned*)&As[r + 8][ks + 2 * tig];
                af[mi][2] = *(const unsigned*)&As[r][ks + 8 + 2 * tig];
                af[mi][3] = *(const unsigned*)&As[r + 8][ks + 8 + 2 * tig];
            }
#pragma unroll
            for (int ni = 0; ni < 4; ni++) {
                int c = wn + ni * 8 + gid;
                bf[ni][0] = *(const unsigned*)&Bs[c][ks + 2 * tig];
                bf[ni][1] = *(const unsigned*)&Bs[c][ks + 8 + 2 * tig];
            }
#pragma unroll
            for (int mi = 0; mi < 4; mi++)
#pragma unroll
                for (int ni = 0; ni < 4; ni++)
                    mma16(acc[mi][ni], af[mi], bf[ni]);
        }
        __syncthreads();
    }

#pragma unroll
    for (int mi = 0; mi < 4; mi++) {
        int r0 = m0 + wm + mi * 16 + gid;
#pragma unroll
        for (int ni = 0; ni < 4; ni++) {
            int c0 = n0 + wn + ni * 8 + 2 * tig;
            float b0 = bias[c0], b1 = bias[c0 + 1];
            if (HEADMAJOR) {
                store_hm(C, r0,     c0,     acc[mi][ni][0] + b0);
                store_hm(C, r0,     c0 + 1, acc[mi][ni][1] + b1);
                store_hm(C, r0 + 8, c0,     acc[mi][ni][2] + b0);
                store_hm(C, r0 + 8, c0 + 1, acc[mi][ni][3] + b1);
            } else {
                C[(size_t)r0 * N + c0]           = acc[mi][ni][0] + b0;
                C[(size_t)r0 * N + c0 + 1]       = acc[mi][ni][1] + b1;
                C[(size_t)(r0 + 8) * N + c0]     = acc[mi][ni][2] + b0;
                C[(size_t)(r0 + 8) * N + c0 + 1] = acc[mi][ni][3] + b1;
            }
        }
    }
}

// ---------------------------------------------------------------------------
// Fused attention, warp-row layout (16x64 S warp tile):
//  - Q A-fragments in registers for the whole kernel (loaded once from gmem)
//  - softmax stats in registers (shuffle-only reductions, no smem/barriers)
//  - S accumulator fragments reused directly as PV A-fragments (no Ps smem)
//  - K/V fragments via ldmatrix.x4 (+.trans for V)
// Pass A: online row max / sumexp. Pass B: recompute S (identical), write
// normalized attn once, ctx += P@V.
// ---------------------------------------------------------------------------
__global__ void __launch_bounds__(256, 2)
fused_attn(const float* __restrict__ Q, const float* __restrict__ Kmat,
           const float* __restrict__ V, const float* __restrict__ mask,
           float* __restrict__ attn, float* __restrict__ ctx)
{
    __shared__ __align__(16) __half Ks[KB][QSTR];
    __shared__ __align__(16) __half Vs[KB][QSTR];

    const int bh = blockIdx.y;
    const int q0 = blockIdx.x * BQ;
    const float* Qb = Q    + (size_t)bh * SEQ * DEPTH;
    const float* Kb = Kmat + (size_t)bh * SEQ * DEPTH;
    const float* Vb = V    + (size_t)bh * SEQ * DEPTH;
    float* attnb = attn + (size_t)bh * SEQ * SEQ;

    const int t = threadIdx.x;
    const int warp = t >> 5, lane = t & 31;
    const int gid = lane >> 2, tig = lane & 3;
    const int r0 = warp * 16 + gid;     // local q row (thread owns r0, r0+8)
    const int r1 = r0 + 8;

    // ldmatrix lane roles
    const int mtx = lane >> 3;          // which of the 4 matrices
    const int mrr = lane & 7;           // row within matrix
    const int ni_off = mtx >> 1;        // 0/1 -> n-tile select within chunk
    const int kh_off = (mtx & 1) * 8;   // k-half select (halves)

    const unsigned ks_base = (unsigned)__cvta_generic_to_shared(&Ks[0][0]);
    const unsigned vs_base = (unsigned)__cvta_generic_to_shared(&Vs[0][0]);

    // ---- Q fragments: loaded once from gmem, kept in registers ----
    unsigned qf[4][4];
#pragma unroll
    for (int s = 0; s < 4; s++) {
        float2 x0 = *(const float2*)&Qb[(size_t)(q0 + r0) * DEPTH + 16 * s + 2 * tig];
        float2 x1 = *(const float2*)&Qb[(size_t)(q0 + r1) * DEPTH + 16 * s + 2 * tig];
        float2 x2 = *(const float2*)&Qb[(size_t)(q0 + r0) * DEPTH + 16 * s + 8 + 2 * tig];
        float2 x3 = *(const float2*)&Qb[(size_t)(q0 + r1) * DEPTH + 16 * s + 8 + 2 * tig];
        qf[s][0] = pack2(x0.x, x0.y);
        qf[s][1] = pack2(x1.x, x1.y);
        qf[s][2] = pack2(x2.x, x2.y);
        qf[s][3] = pack2(x3.x, x3.y);
    }

    const float* mrow0 = mask + (size_t)(q0 + r0) * SEQ;
    const float* mrow1 = mask + (size_t)(q0 + r1) * SEQ;

    float m0 = -1e30f, m1 = -1e30f, l0 = 0.f, l1 = 0.f;

    // ------------------------- Pass A: stats -------------------------
    for (int kb = 0; kb < NKB; kb++) {
        const int k0 = kb * KB;
#pragma unroll
        for (int i = 0; i < 4; i++) {
            int idx = t + i * 256;
            int r = idx >> 4, c4 = (idx & 15) << 2;
            float4 a = *(const float4*)&Kb[(size_t)(k0 + r) * DEPTH + c4];
            *(uint2*)&Ks[r][c4] = make_uint2(pack2(a.x, a.y), pack2(a.z, a.w));
        }
        __syncthreads();

        float acc[8][4];
#pragma unroll
        for (int ni = 0; ni < 8; ni++)
#pragma unroll
            for (int r = 0; r < 4; r++) acc[ni][r] = 0.f;

#pragma unroll
        for (int s = 0; s < 4; s++) {
            unsigned bf[8][2];
#pragma unroll
            for (int i = 0; i < 4; i++) {
                unsigned addr = ks_base +
                    (unsigned)((((2 * i + ni_off) * 8 + mrr) * QSTR + 16 * s + kh_off) * 2);
                ldsm_x4(bf[2 * i][0], bf[2 * i][1], bf[2 * i + 1][0], bf[2 * i + 1][1], addr);
            }
#pragma unroll
            for (int ni = 0; ni < 8; ni++) mma16(acc[ni], qf[s], bf[ni]);
        }

        float rm0 = -1e30f, rm1 = -1e30f;
#pragma unroll
        for (int ni = 0; ni < 8; ni++) {
            int c = ni * 8 + 2 * tig;
            float2 mv0 = *(const float2*)&mrow0[k0 + c];
            float2 mv1 = *(const float2*)&mrow1[k0 + c];
            acc[ni][0] = acc[ni][0] * 0.125f + mv0.x * (-1e9f);
            acc[ni][1] = acc[ni][1] * 0.125f + mv0.y * (-1e9f);
            acc[ni][2] = acc[ni][2] * 0.125f + mv1.x * (-1e9f);
            acc[ni][3] = acc[ni][3] * 0.125f + mv1.y * (-1e9f);
            rm0 = fmaxf(rm0, fmaxf(acc[ni][0], acc[ni][1]));
            rm1 = fmaxf(rm1, fmaxf(acc[ni][2], acc[ni][3]));
        }
        rm0 = fmaxf(rm0, __shfl_xor_sync(0xffffffffu, rm0, 1));
        rm0 = fmaxf(rm0, __shfl_xor_sync(0xffffffffu, rm0, 2));
        rm1 = fmaxf(rm1, __shfl_xor_sync(0xffffffffu, rm1, 1));
        rm1 = fmaxf(rm1, __shfl_xor_sync(0xffffffffu, rm1, 2));

        float mn0 = fmaxf(m0, rm0), mn1 = fmaxf(m1, rm1);
        float sc0 = __expf(m0 - mn0), sc1 = __expf(m1 - mn1);
        m0 = mn0; m1 = mn1;

        float ts0 = 0.f, ts1 = 0.f;
#pragma unroll
        for (int ni = 0; ni < 8; ni++) {
            ts0 += __expf(acc[ni][0] - m0) + __expf(acc[ni][1] - m0);
            ts1 += __expf(acc[ni][2] - m1) + __expf(acc[ni][3] - m1);
        }
        ts0 += __shfl_xor_sync(0xffffffffu, ts0, 1);
        ts0 += __shfl_xor_sync(0xffffffffu, ts0, 2);
        ts1 += __shfl_xor_sync(0xffffffffu, ts1, 1);
        ts1 += __shfl_xor_sync(0xffffffffu, ts1, 2);

        l0 = l0 * sc0 + ts0;
        l1 = l1 * sc1 + ts1;
        __syncthreads();
    }

    const float inv0 = 1.0f / l0;
    const float inv1 = 1.0f / l1;

    // ------------------------- Pass B: write + PV -------------------------
    float cacc[8][4];
#pragma unroll
    for (int ni = 0; ni < 8; ni++)
#pragma unroll
        for (int r = 0; r < 4; r++) cacc[ni][r] = 0.f;

    for (int kb = 0; kb < NKB; kb++) {
        const int k0 = kb * KB;
#pragma unroll
        for (int i = 0; i < 4; i++) {
            int idx = t + i * 256;
            int r = idx >> 4, c4 = (idx & 15) << 2;
            float4 a = *(const float4*)&Kb[(size_t)(k0 + r) * DEPTH + c4];
            *(uint2*)&Ks[r][c4] = make_uint2(pack2(a.x, a.y), pack2(a.z, a.w));
            float4 b = *(const float4*)&Vb[(size_t)(k0 + r) * DEPTH + c4];
            *(uint2*)&Vs[r][c4] = make_uint2(pack2(b.x, b.y), pack2(b.z, b.w));
        }
        __syncthreads();

        float acc[8][4];
#pragma unroll
        for (int ni = 0; ni < 8; ni++)
#pragma unroll
            for (int r = 0; r < 4; r++) acc[ni][r] = 0.f;

#pragma unroll
        for (int s = 0; s < 4; s++) {
            unsigned bf[8][2];
#pragma unroll
            for (int i = 0; i < 4; i++) {
                unsigned addr = ks_base +
                    (unsigned)((((2 * i + ni_off) * 8 + mrr) * QSTR + 16 * s + kh_off) * 2);
                ldsm_x4(bf[2 * i][0], bf[2 * i][1], bf[2 * i + 1][0], bf[2 * i + 1][1], addr);
            }
#pragma unroll
            for (int ni = 0; ni < 8; ni++) mma16(acc[ni], qf[s], bf[ni]);
        }

        // p = exp(s - m) * inv ; write attn ; repack acc frags -> PV A frags
        unsigned pf[4][4];
#pragma unroll
        for (int ni = 0; ni < 8; ni++) {
            int c = ni * 8 + 2 * tig;
            int kg = k0 + c;
            float2 mv0 = *(const float2*)&mrow0[kg];
            float2 mv1 = *(const float2*)&mrow1[kg];
            float p00 = __expf(acc[ni][0] * 0.125f + mv0.x * (-1e9f) - m0) * inv0;
            float p01 = __expf(acc[ni][1] * 0.125f + mv0.y * (-1e9f) - m0) * inv0;
            float p10 = __expf(acc[ni][2] * 0.125f + mv1.x * (-1e9f) - m1) * inv1;
            float p11 = __expf(acc[ni][3] * 0.125f + mv1.y * (-1e9f) - m1) * inv1;
            *(float2*)&attnb[(size_t)(q0 + r0) * SEQ + kg] = make_float2(p00, p01);
            *(float2*)&attnb[(size_t)(q0 + r1) * SEQ + kg] = make_float2(p10, p11);
            int sp = ni >> 1;
            if (ni & 1) { pf[sp][2] = pack2(p00, p01); pf[sp][3] = pack2(p10, p11); }
            else        { pf[sp][0] = pack2(p00, p01); pf[sp][1] = pack2(p10, p11); }
        }

        // ctx += P @ V  (V B-frags via ldmatrix.trans)
#pragma unroll
        for (int s = 0; s < 4; s++) {
            unsigned vbf[8][2];
#pragma unroll
            for (int i = 0; i < 4; i++) {
                unsigned addr = vs_base +
                    (unsigned)(((16 * s + kh_off + mrr) * QSTR + (2 * i + ni_off) * 8) * 2);
                ldsm_x4_t(vbf[2 * i][0], vbf[2 * i][1], vbf[2 * i + 1][0], vbf[2 * i + 1][1], addr);
            }
#pragma unroll
            for (int ni = 0; ni < 8; ni++) mma16(cacc[ni], pf[s], vbf[ni]);
        }
        __syncthreads();
    }

    // write ctx (b, s, h*64 + d)
    const int b = bh >> 4;
    const int hh = bh & 15;
#pragma unroll
    for (int ni = 0; ni < 8; ni++) {
        int d0 = ni * 8 + 2 * tig;
        *(float2*)&ctx[((size_t)b * SEQ + q0 + r0) * D_MODEL + hh * DEPTH + d0] =
            make_float2(cacc[ni][0], cacc[ni][1]);
        *(float2*)&ctx[((size_t)b * SEQ + q0 + r1) * D_MODEL + hh * DEPTH + d0] =
            make_float2(cacc[ni][2], cacc[ni][3]);
    }
}

// ---------------------------------------------------------------------------
// Inputs (metadata order): v, k, q, mask, wq_w, wq_b, wk_w, wk_b, wv_w, wv_b,
//                          dense_w, dense_b
// Output: [out (B*S*D_MODEL) | attn (B*H*S*S)] fp32
// ---------------------------------------------------------------------------
extern "C" void kernel_launch(void* const* d_in, const int* in_sizes, int n_in,
                              void* d_out, int out_size)
{
    const float* v_in = (const float*)d_in[0];
    const float* k_in = (const float*)d_in[1];
    const float* q_in = (const float*)d_in[2];
    const float* mask = (const float*)d_in[3];
    const float* wq_w = (const float*)d_in[4];
    const float* wq_b = (const float*)d_in[5];
    const float* wk_w = (const float*)d_in[6];
    const float* wk_b = (const float*)d_in[7];
    const float* wv_w = (const float*)d_in[8];
    const float* wv_b = (const float*)d_in[9];
    const float* dw   = (const float*)d_in[10];
    const float* db   = (const float*)d_in[11];

    float* out  = (float*)d_out;
    float* attn = out + (size_t)BATCH * SEQ * D_MODEL;

    float *gq, *gk, *gv, *gctx;
    cudaGetSymbolAddress((void**)&gq,   g_Q);
    cudaGetSymbolAddress((void**)&gk,   g_K);
    cudaGetSymbolAddress((void**)&gv,   g_V);
    cudaGetSymbolAddress((void**)&gctx, g_CTX);

    const int M = BATCH * SEQ;  // 8192

    dim3 gp(D_MODEL / 128, M / 128);     // (8, 64)
    gemm_f16<1><<<gp, 256>>>(q_in, wq_w, wq_b, gq, M, D_MODEL, D_MODEL);
    gemm_f16<1><<<gp, 256>>>(k_in, wk_w, wk_b, gk, M, D_MODEL, D_MODEL);
    gemm_f16<1><<<gp, 256>>>(v_in, wv_w, wv_b, gv, M, D_MODEL, D_MODEL);

    dim3 gf(SEQ / BQ, BHN);              // (16, 64)
    fused_attn<<<gf, 256>>>(gq, gk, gv, mask, attn, gctx);

    gemm_f16<0><<<gp, 256>>>(gctx, dw, db, out, M, D_MODEL, D_MODEL);
}

// round 11
// speedup vs baseline: 3.7434x; 1.0478x over previous
#include <cuda_runtime.h>
#include <cuda_fp16.h>
#include <cstddef>

#define D_MODEL 1024
#define NUM_HEADS 16
#define DEPTH 64
#define BATCH 4
#define SEQ 2048
#define BHN (BATCH * NUM_HEADS)
#define BQ 128
#define KB 64
#define NKB (SEQ / KB)
#define QSTR 72   // half stride (64 + 8 pad) -> conflict-free ldmatrix rows

// Scratch (device globals; no allocation allowed) -- HALF precision
__device__ __half g_Q[(size_t)BHN * SEQ * DEPTH];       // (b,h,s,d)
__device__ __half g_K[(size_t)BHN * SEQ * DEPTH];
__device__ __half g_V[(size_t)BHN * SEQ * DEPTH];
__device__ __half g_CTX[(size_t)BATCH * SEQ * D_MODEL]; // (b,s,h*64+d)

// ---------------------------------------------------------------------------
// FP16 helpers
// ---------------------------------------------------------------------------
__device__ __forceinline__ unsigned pack2(float a, float b) {
    __half2 h = __floats2half2_rn(a, b);
    return *(unsigned*)&h;
}

// D(16x8) += A(16x16) @ B(16x8)   fp16 inputs, fp32 accum
__device__ __forceinline__ void mma16(float* d, const unsigned* a, const unsigned* b) {
    asm volatile(
        "mma.sync.aligned.m16n8k16.row.col.f32.f16.f16.f32 "
        "{%0,%1,%2,%3}, {%4,%5,%6,%7}, {%8,%9}, {%0,%1,%2,%3};\n"
        : "+f"(d[0]), "+f"(d[1]), "+f"(d[2]), "+f"(d[3])
        : "r"(a[0]), "r"(a[1]), "r"(a[2]), "r"(a[3]), "r"(b[0]), "r"(b[1]));
}

__device__ __forceinline__ void ldsm_x4(unsigned& r0, unsigned& r1,
                                        unsigned& r2, unsigned& r3, unsigned addr) {
    asm volatile("ldmatrix.sync.aligned.m8n8.x4.shared.b16 {%0,%1,%2,%3}, [%4];"
                 : "=r"(r0), "=r"(r1), "=r"(r2), "=r"(r3) : "r"(addr));
}
__device__ __forceinline__ void ldsm_x4_t(unsigned& r0, unsigned& r1,
                                          unsigned& r2, unsigned& r3, unsigned addr) {
    asm volatile("ldmatrix.sync.aligned.m8n8.x4.trans.shared.b16 {%0,%1,%2,%3}, [%4];"
                 : "=r"(r0), "=r"(r1), "=r"(r2), "=r"(r3) : "r"(addr));
}

// ---------------------------------------------------------------------------
// GEMM: C = A(MxK) @ W(NxK)^T + bias  (fp16 mma, fp32 accum, ldmatrix frags)
// TA = float or __half (A operand); TO = float or __half (output).
// HEADMAJOR scatters output to (b,h,s,d) half layout.
// Tile 128x128, BK=32, 8 warps (2x4), warp tile 64x32.
// ---------------------------------------------------------------------------
#define GSTR 40   // half stride of gemm smem rows (BK=32 + 8 pad)

template <typename TA, int HEADMAJOR, typename TO>
__global__ void __launch_bounds__(256, 2)
gemm_f16(const TA* __restrict__ A, const float* __restrict__ W,
         const float* __restrict__ bias, TO* __restrict__ C,
         int M, int N, int K)
{
    const int BM = 128, BN = 128, BK = 32;
    __shared__ __align__(16) __half As[BM][GSTR];
    __shared__ __align__(16) __half Bs[BN][GSTR];

    const int m0 = blockIdx.y * BM;
    const int n0 = blockIdx.x * BN;
    const int t = threadIdx.x;
    const int warp = t >> 5, lane = t & 31;
    const int wm = (warp >> 2) * 64, wn = (warp & 3) * 32;
    const int gid = lane >> 2, tig = lane & 3;

    // ldmatrix lane roles
    const int mtx = lane >> 3;          // 0..3
    const int mrr = lane & 7;           // row within 8x8 matrix
    const int a_roff = (mtx & 1) * 8;   // A: row offset
    const int a_koff = (mtx >> 1) * 8;  // A: k offset
    const int ni_off = mtx >> 1;        // B: n-tile select
    const int kh_off = (mtx & 1) * 8;   // B: k-half select

    const unsigned as_base = (unsigned)__cvta_generic_to_shared(&As[0][0]);
    const unsigned bs_base = (unsigned)__cvta_generic_to_shared(&Bs[0][0]);

    float acc[4][4][4];
#pragma unroll
    for (int mi = 0; mi < 4; mi++)
#pragma unroll
        for (int ni = 0; ni < 4; ni++)
#pragma unroll
            for (int r = 0; r < 4; r++) acc[mi][ni][r] = 0.f;

    for (int k0 = 0; k0 < K; k0 += BK) {
        // stage A
        if constexpr (sizeof(TA) == 4) {
#pragma unroll
            for (int i = 0; i < 4; i++) {
                int idx = t + i * 256;              // 0..1023
                int r = idx >> 3;                   // 0..127
                int c4 = (idx & 7) << 2;
                float4 a = *(const float4*)&A[(size_t)(m0 + r) * K + k0 + c4];
                *(uint2*)&As[r][c4] = make_uint2(pack2(a.x, a.y), pack2(a.z, a.w));
            }
        } else {
#pragma unroll
            for (int i = 0; i < 2; i++) {
                int idx = t + i * 256;              // 0..511
                int r = idx >> 2;                   // 0..127
                int c8 = (idx & 3) << 3;            // 0,8,16,24
                *(uint4*)&As[r][c8] = *(const uint4*)&A[(size_t)(m0 + r) * K + k0 + c8];
            }
        }
        // stage W (always float)
#pragma unroll
        for (int i = 0; i < 4; i++) {
            int idx = t + i * 256;
            int r = idx >> 3;
            int c4 = (idx & 7) << 2;
            float4 b = *(const float4*)&W[(size_t)(n0 + r) * K + k0 + c4];
            *(uint2*)&Bs[r][c4] = make_uint2(pack2(b.x, b.y), pack2(b.z, b.w));
        }
        __syncthreads();

#pragma unroll
        for (int ks = 0; ks < BK; ks += 16) {
            unsigned af[4][4], bf[4][2];
#pragma unroll
            for (int mi = 0; mi < 4; mi++) {
                unsigned addr = as_base +
                    (unsigned)(((wm + mi * 16 + a_roff + mrr) * GSTR + ks + a_koff) * 2);
                ldsm_x4(af[mi][0], af[mi][1], af[mi][2], af[mi][3], addr);
            }
#pragma unroll
            for (int i = 0; i < 2; i++) {
                unsigned addr = bs_base +
                    (unsigned)(((wn + (2 * i + ni_off) * 8 + mrr) * GSTR + ks + kh_off) * 2);
                ldsm_x4(bf[2 * i][0], bf[2 * i][1], bf[2 * i + 1][0], bf[2 * i + 1][1], addr);
            }
#pragma unroll
            for (int mi = 0; mi < 4; mi++)
#pragma unroll
                for (int ni = 0; ni < 4; ni++)
                    mma16(acc[mi][ni], af[mi], bf[ni]);
        }
        __syncthreads();
    }

#pragma unroll
    for (int mi = 0; mi < 4; mi++) {
        int r0 = m0 + wm + mi * 16 + gid;
#pragma unroll
        for (int ni = 0; ni < 4; ni++) {
            int c0 = n0 + wn + ni * 8 + 2 * tig;
            float b0 = bias[c0], b1 = bias[c0 + 1];
            if constexpr (HEADMAJOR) {
                // half output at (b,h,s,d); d pairs contiguous
                int h = c0 >> 6, d = c0 & (DEPTH - 1);
#pragma unroll
                for (int rr = 0; rr < 2; rr++) {
                    int m = r0 + rr * 8;
                    int bb = m >> 11, s = m & (SEQ - 1);
                    __half* dst = (__half*)C +
                        (((size_t)(bb * NUM_HEADS + h)) * SEQ + s) * DEPTH + d;
                    *(unsigned*)dst = pack2(acc[mi][ni][rr * 2] + b0,
                                            acc[mi][ni][rr * 2 + 1] + b1);
                }
            } else {
                if constexpr (sizeof(TO) == 4) {
                    float* dst = (float*)C;
                    *(float2*)&dst[(size_t)r0 * N + c0] =
                        make_float2(acc[mi][ni][0] + b0, acc[mi][ni][1] + b1);
                    *(float2*)&dst[(size_t)(r0 + 8) * N + c0] =
                        make_float2(acc[mi][ni][2] + b0, acc[mi][ni][3] + b1);
                } else {
                    __half* dst = (__half*)C;
                    *(unsigned*)&dst[(size_t)r0 * N + c0] =
                        pack2(acc[mi][ni][0] + b0, acc[mi][ni][1] + b1);
                    *(unsigned*)&dst[(size_t)(r0 + 8) * N + c0] =
                        pack2(acc[mi][ni][2] + b0, acc[mi][ni][3] + b1);
                }
            }
        }
    }
}

// ---------------------------------------------------------------------------
// Fused attention, warp-row layout (16x64 S warp tile), half-native Q/K/V:
//  - Q A-fragments loaded once from gmem (half2), kept in registers
//  - softmax stats in registers (shuffle-only reductions)
//  - S accumulator fragments reused directly as PV A-fragments
//  - K/V fragments via ldmatrix.x4 (+.trans for V); staging = raw uint4 copies
// ---------------------------------------------------------------------------
__global__ void __launch_bounds__(256, 2)
fused_attn(const __half* __restrict__ Q, const __half* __restrict__ Kmat,
           const __half* __restrict__ V, const float* __restrict__ mask,
           float* __restrict__ attn, __half* __restrict__ ctx)
{
    __shared__ __align__(16) __half Ks[KB][QSTR];
    __shared__ __align__(16) __half Vs[KB][QSTR];

    const int bh = blockIdx.y;
    const int q0 = blockIdx.x * BQ;
    const __half* Qb = Q    + (size_t)bh * SEQ * DEPTH;
    const __half* Kb = Kmat + (size_t)bh * SEQ * DEPTH;
    const __half* Vb = V    + (size_t)bh * SEQ * DEPTH;
    float* attnb = attn + (size_t)bh * SEQ * SEQ;

    const int t = threadIdx.x;
    const int warp = t >> 5, lane = t & 31;
    const int gid = lane >> 2, tig = lane & 3;
    const int r0 = warp * 16 + gid;     // local q row (thread owns r0, r0+8)
    const int r1 = r0 + 8;

    const int mtx = lane >> 3;
    const int mrr = lane & 7;
    const int ni_off = mtx >> 1;
    const int kh_off = (mtx & 1) * 8;

    const unsigned ks_base = (unsigned)__cvta_generic_to_shared(&Ks[0][0]);
    const unsigned vs_base = (unsigned)__cvta_generic_to_shared(&Vs[0][0]);

    // ---- Q fragments: loaded once (half2 direct), kept in registers ----
    unsigned qf[4][4];
#pragma unroll
    for (int s = 0; s < 4; s++) {
        qf[s][0] = *(const unsigned*)&Qb[(size_t)(q0 + r0) * DEPTH + 16 * s + 2 * tig];
        qf[s][1] = *(const unsigned*)&Qb[(size_t)(q0 + r1) * DEPTH + 16 * s + 2 * tig];
        qf[s][2] = *(const unsigned*)&Qb[(size_t)(q0 + r0) * DEPTH + 16 * s + 8 + 2 * tig];
        qf[s][3] = *(const unsigned*)&Qb[(size_t)(q0 + r1) * DEPTH + 16 * s + 8 + 2 * tig];
    }

    const float* mrow0 = mask + (size_t)(q0 + r0) * SEQ;
    const float* mrow1 = mask + (size_t)(q0 + r1) * SEQ;

    float m0 = -1e30f, m1 = -1e30f, l0 = 0.f, l1 = 0.f;

    // ------------------------- Pass A: stats -------------------------
    for (int kb = 0; kb < NKB; kb++) {
        const int k0 = kb * KB;
#pragma unroll
        for (int i = 0; i < 2; i++) {
            int idx = t + i * 256;             // 0..511
            int r = idx >> 3;                  // 0..63
            int c8 = (idx & 7) << 3;           // 0..56
            *(uint4*)&Ks[r][c8] = *(const uint4*)&Kb[(size_t)(k0 + r) * DEPTH + c8];
        }
        __syncthreads();

        float acc[8][4];
#pragma unroll
        for (int ni = 0; ni < 8; ni++)
#pragma unroll
            for (int r = 0; r < 4; r++) acc[ni][r] = 0.f;

#pragma unroll
        for (int s = 0; s < 4; s++) {
            unsigned bf[8][2];
#pragma unroll
            for (int i = 0; i < 4; i++) {
                unsigned addr = ks_base +
                    (unsigned)((((2 * i + ni_off) * 8 + mrr) * QSTR + 16 * s + kh_off) * 2);
                ldsm_x4(bf[2 * i][0], bf[2 * i][1], bf[2 * i + 1][0], bf[2 * i + 1][1], addr);
            }
#pragma unroll
            for (int ni = 0; ni < 8; ni++) mma16(acc[ni], qf[s], bf[ni]);
        }

        float rm0 = -1e30f, rm1 = -1e30f;
#pragma unroll
        for (int ni = 0; ni < 8; ni++) {
            int c = ni * 8 + 2 * tig;
            float2 mv0 = *(const float2*)&mrow0[k0 + c];
            float2 mv1 = *(const float2*)&mrow1[k0 + c];
            acc[ni][0] = acc[ni][0] * 0.125f + mv0.x * (-1e9f);
            acc[ni][1] = acc[ni][1] * 0.125f + mv0.y * (-1e9f);
            acc[ni][2] = acc[ni][2] * 0.125f + mv1.x * (-1e9f);
            acc[ni][3] = acc[ni][3] * 0.125f + mv1.y * (-1e9f);
            rm0 = fmaxf(rm0, fmaxf(acc[ni][0], acc[ni][1]));
            rm1 = fmaxf(rm1, fmaxf(acc[ni][2], acc[ni][3]));
        }
        rm0 = fmaxf(rm0, __shfl_xor_sync(0xffffffffu, rm0, 1));
        rm0 = fmaxf(rm0, __shfl_xor_sync(0xffffffffu, rm0, 2));
        rm1 = fmaxf(rm1, __shfl_xor_sync(0xffffffffu, rm1, 1));
        rm1 = fmaxf(rm1, __shfl_xor_sync(0xffffffffu, rm1, 2));

        float mn0 = fmaxf(m0, rm0), mn1 = fmaxf(m1, rm1);
        float sc0 = __expf(m0 - mn0), sc1 = __expf(m1 - mn1);
        m0 = mn0; m1 = mn1;

        float ts0 = 0.f, ts1 = 0.f;
#pragma unroll
        for (int ni = 0; ni < 8; ni++) {
            ts0 += __expf(acc[ni][0] - m0) + __expf(acc[ni][1] - m0);
            ts1 += __expf(acc[ni][2] - m1) + __expf(acc[ni][3] - m1);
        }
        ts0 += __shfl_xor_sync(0xffffffffu, ts0, 1);
        ts0 += __shfl_xor_sync(0xffffffffu, ts0, 2);
        ts1 += __shfl_xor_sync(0xffffffffu, ts1, 1);
        ts1 += __shfl_xor_sync(0xffffffffu, ts1, 2);

        l0 = l0 * sc0 + ts0;
        l1 = l1 * sc1 + ts1;
        __syncthreads();
    }

    const float inv0 = 1.0f / l0;
    const float inv1 = 1.0f / l1;

    // ------------------------- Pass B: write + PV -------------------------
    float cacc[8][4];
#pragma unroll
    for (int ni = 0; ni < 8; ni++)
#pragma unroll
        for (int r = 0; r < 4; r++) cacc[ni][r] = 0.f;

    for (int kb = 0; kb < NKB; kb++) {
        const int k0 = kb * KB;
#pragma unroll
        for (int i = 0; i < 2; i++) {
            int idx = t + i * 256;
            int r = idx >> 3, c8 = (idx & 7) << 3;
            *(uint4*)&Ks[r][c8] = *(const uint4*)&Kb[(size_t)(k0 + r) * DEPTH + c8];
            *(uint4*)&Vs[r][c8] = *(const uint4*)&Vb[(size_t)(k0 + r) * DEPTH + c8];
        }
        __syncthreads();

        float acc[8][4];
#pragma unroll
        for (int ni = 0; ni < 8; ni++)
#pragma unroll
            for (int r = 0; r < 4; r++) acc[ni][r] = 0.f;

#pragma unroll
        for (int s = 0; s < 4; s++) {
            unsigned bf[8][2];
#pragma unroll
            for (int i = 0; i < 4; i++) {
                unsigned addr = ks_base +
                    (unsigned)((((2 * i + ni_off) * 8 + mrr) * QSTR + 16 * s + kh_off) * 2);
                ldsm_x4(bf[2 * i][0], bf[2 * i][1], bf[2 * i + 1][0], bf[2 * i + 1][1], addr);
            }
#pragma unroll
            for (int ni = 0; ni < 8; ni++) mma16(acc[ni], qf[s], bf[ni]);
        }

        // p = exp(s - m) * inv ; write attn ; repack acc frags -> PV A frags
        unsigned pf[4][4];
#pragma unroll
        for (int ni = 0; ni < 8; ni++) {
            int c = ni * 8 + 2 * tig;
            int kg = k0 + c;
            float2 mv0 = *(const float2*)&mrow0[kg];
            float2 mv1 = *(const float2*)&mrow1[kg];
            float p00 = __expf(acc[ni][0] * 0.125f + mv0.x * (-1e9f) - m0) * inv0;
            float p01 = __expf(acc[ni][1] * 0.125f + mv0.y * (-1e9f) - m0) * inv0;
            float p10 = __expf(acc[ni][2] * 0.125f + mv1.x * (-1e9f) - m1) * inv1;
            float p11 = __expf(acc[ni][3] * 0.125f + mv1.y * (-1e9f) - m1) * inv1;
            *(float2*)&attnb[(size_t)(q0 + r0) * SEQ + kg] = make_float2(p00, p01);
            *(float2*)&attnb[(size_t)(q0 + r1) * SEQ + kg] = make_float2(p10, p11);
            int sp = ni >> 1;
            if (ni & 1) { pf[sp][2] = pack2(p00, p01); pf[sp][3] = pack2(p10, p11); }
            else        { pf[sp][0] = pack2(p00, p01); pf[sp][1] = pack2(p10, p11); }
        }

        // ctx += P @ V  (V B-frags via ldmatrix.trans)
#pragma unroll
        for (int s = 0; s < 4; s++) {
            unsigned vbf[8][2];
#pragma unroll
            for (int i = 0; i < 4; i++) {
                unsigned addr = vs_base +
                    (unsigned)(((16 * s + kh_off + mrr) * QSTR + (2 * i + ni_off) * 8) * 2);
                ldsm_x4_t(vbf[2 * i][0], vbf[2 * i][1], vbf[2 * i + 1][0], vbf[2 * i + 1][1], addr);
            }
#pragma unroll
            for (int ni = 0; ni < 8; ni++) mma16(cacc[ni], pf[s], vbf[ni]);
        }
        __syncthreads();
    }

    // write ctx (b, s, h*64 + d) as half
    const int b = bh >> 4;
    const int hh = bh & 15;
#pragma unroll
    for (int ni = 0; ni < 8; ni++) {
        int d0 = ni * 8 + 2 * tig;
        *(unsigned*)&ctx[((size_t)b * SEQ + q0 + r0) * D_MODEL + hh * DEPTH + d0] =
            pack2(cacc[ni][0], cacc[ni][1]);
        *(unsigned*)&ctx[((size_t)b * SEQ + q0 + r1) * D_MODEL + hh * DEPTH + d0] =
            pack2(cacc[ni][2], cacc[ni][3]);
    }
}

// ---------------------------------------------------------------------------
// Inputs (metadata order): v, k, q, mask, wq_w, wq_b, wk_w, wk_b, wv_w, wv_b,
//                          dense_w, dense_b
// Output: [out (B*S*D_MODEL) | attn (B*H*S*S)] fp32
// ---------------------------------------------------------------------------
extern "C" void kernel_launch(void* const* d_in, const int* in_sizes, int n_in,
                              void* d_out, int out_size)
{
    const float* v_in = (const float*)d_in[0];
    const float* k_in = (const float*)d_in[1];
    const float* q_in = (const float*)d_in[2];
    const float* mask = (const float*)d_in[3];
    const float* wq_w = (const float*)d_in[4];
    const float* wq_b = (const float*)d_in[5];
    const float* wk_w = (const float*)d_in[6];
    const float* wk_b = (const float*)d_in[7];
    const float* wv_w = (const float*)d_in[8];
    const float* wv_b = (const float*)d_in[9];
    const float* dw   = (const float*)d_in[10];
    const float* db   = (const float*)d_in[11];

    float* out  = (float*)d_out;
    float* attn = out + (size_t)BATCH * SEQ * D_MODEL;

    __half *gq, *gk, *gv, *gctx;
    cudaGetSymbolAddress((void**)&gq,   g_Q);
    cudaGetSymbolAddress((void**)&gk,   g_K);
    cudaGetSymbolAddress((void**)&gv,   g_V);
    cudaGetSymbolAddress((void**)&gctx, g_CTX);

    const int M = BATCH * SEQ;  // 8192

    dim3 gp(D_MODEL / 128, M / 128);     // (8, 64)
    gemm_f16<float, 1, __half><<<gp, 256>>>(q_in, wq_w, wq_b, gq, M, D_MODEL, D_MODEL);
    gemm_f16<float, 1, __half><<<gp, 256>>>(k_in, wk_w, wk_b, gk, M, D_MODEL, D_MODEL);
    gemm_f16<float, 1, __half><<<gp, 256>>>(v_in, wv_w, wv_b, gv, M, D_MODEL, D_MODEL);

    dim3 gf(SEQ / BQ, BHN);              // (16, 64)
    fused_attn<<<gf, 256>>>(gq, gk, gv, mask, attn, gctx);

    gemm_f16<__half, 0, float><<<gp, 256>>>(gctx, dw, db, out, M, D_MODEL, D_MODEL);
}

// round 13
// speedup vs baseline: 4.1379x; 1.1054x over previous
#include <cuda_runtime.h>
#include <cuda_fp16.h>
#include <cstddef>

#define D_MODEL 1024
#define NUM_HEADS 16
#define DEPTH 64
#define BATCH 4
#define SEQ 2048
#define BHN (BATCH * NUM_HEADS)
#define BQ 128
#define KBB 128                 // K-rows staged per pipeline stage (2 chunks of 64)
#define NKB (SEQ / KBB)         // 16
#define QSTR 72                 // half stride (64 + 8 pad) -> conflict-free ldmatrix
#define GSTR 40                 // gemm smem half stride (32 + 8 pad)
#define MTOT (BATCH * SEQ)      // 8192

// Scratch (device globals; no allocation allowed)
__device__ __half g_Q[(size_t)BHN * SEQ * DEPTH];
__device__ __half g_K[(size_t)BHN * SEQ * DEPTH];
__device__ __half g_V[(size_t)BHN * SEQ * DEPTH];
__device__ __half g_CTX[(size_t)BATCH * SEQ * D_MODEL];
__device__ __half g_XH[3][(size_t)MTOT * D_MODEL];      // v,k,q inputs as half
__device__ __half g_WH[4][(size_t)D_MODEL * D_MODEL];   // wq,wk,wv,dense as half

// ---------------------------------------------------------------------------
// Helpers
// ---------------------------------------------------------------------------
__device__ __forceinline__ unsigned pack2(float a, float b) {
    __half2 h = __floats2half2_rn(a, b);
    return *(unsigned*)&h;
}

__device__ __forceinline__ void mma16(float* d, const unsigned* a, const unsigned* b) {
    asm volatile(
        "mma.sync.aligned.m16n8k16.row.col.f32.f16.f16.f32 "
        "{%0,%1,%2,%3}, {%4,%5,%6,%7}, {%8,%9}, {%0,%1,%2,%3};\n"
        : "+f"(d[0]), "+f"(d[1]), "+f"(d[2]), "+f"(d[3])
        : "r"(a[0]), "r"(a[1]), "r"(a[2]), "r"(a[3]), "r"(b[0]), "r"(b[1]));
}

__device__ __forceinline__ void ldsm_x4(unsigned& r0, unsigned& r1,
                                        unsigned& r2, unsigned& r3, unsigned addr) {
    asm volatile("ldmatrix.sync.aligned.m8n8.x4.shared.b16 {%0,%1,%2,%3}, [%4];"
                 : "=r"(r0), "=r"(r1), "=r"(r2), "=r"(r3) : "r"(addr));
}
__device__ __forceinline__ void ldsm_x4_t(unsigned& r0, unsigned& r1,
                                          unsigned& r2, unsigned& r3, unsigned addr) {
    asm volatile("ldmatrix.sync.aligned.m8n8.x4.trans.shared.b16 {%0,%1,%2,%3}, [%4];"
                 : "=r"(r0), "=r"(r1), "=r"(r2), "=r"(r3) : "r"(addr));
}

__device__ __forceinline__ void cp16(unsigned smem_addr, const void* gptr) {
    asm volatile("cp.async.cg.shared.global [%0], [%1], 16;"
                 :: "r"(smem_addr), "l"(gptr));
}
__device__ __forceinline__ void cp_commit() {
    asm volatile("cp.async.commit_group;");
}
__device__ __forceinline__ void cp_wait0() {
    asm volatile("cp.async.wait_group 0;");
}

// ---------------------------------------------------------------------------
// Convert fp32 tensors to half (inputs + weights), one sweep.
// ---------------------------------------------------------------------------
struct ConvJobs {
    const float* src[7];
    __half* dst[7];
    int n[7];
};

__global__ void __launch_bounds__(256)
convert_f2h(ConvJobs jobs)
{
    const int z = blockIdx.z;
    const float* s = jobs.src[z];
    __half* d = jobs.dst[z];
    const int n = jobs.n[z];
    for (int i = (blockIdx.x * 256 + threadIdx.x) * 4; i < n; i += gridDim.x * 256 * 4) {
        float4 v = *(const float4*)(s + i);
        *(uint2*)(d + i) = make_uint2(pack2(v.x, v.y), pack2(v.z, v.w));
    }
}

// ---------------------------------------------------------------------------
// GEMM: C = A(MxK) @ W(NxK)^T + bias  (all-half operands, fp32 accum,
// ldmatrix fragments, 2-stage cp.async pipeline).
// Tile 128x128, BK=32, 8 warps (2x4), warp tile 64x32.
// ---------------------------------------------------------------------------
template <int HEADMAJOR, typename TO>
__global__ void __launch_bounds__(256, 2)
gemm_f16(const __half* __restrict__ A, const __half* __restrict__ W,
         const float* __restrict__ bias, TO* __restrict__ C,
         int M, int N, int K)
{
    const int BM = 128, BN = 128, BK = 32;
    __shared__ __align__(16) __half As[2][BM][GSTR];
    __shared__ __align__(16) __half Bs[2][BN][GSTR];

    const int m0 = blockIdx.y * BM;
    const int n0 = blockIdx.x * BN;
    const int t = threadIdx.x;
    const int warp = t >> 5, lane = t & 31;
    const int wm = (warp >> 2) * 64, wn = (warp & 3) * 32;
    const int gid = lane >> 2, tig = lane & 3;

    const int mtx = lane >> 3;
    const int mrr = lane & 7;
    const int a_roff = (mtx & 1) * 8;
    const int a_koff = (mtx >> 1) * 8;
    const int ni_off = mtx >> 1;
    const int kh_off = (mtx & 1) * 8;

    const unsigned as_base = (unsigned)__cvta_generic_to_shared(&As[0][0][0]);
    const unsigned bs_base = (unsigned)__cvta_generic_to_shared(&Bs[0][0][0]);
    const unsigned a_buf_stride = BM * GSTR * 2;   // bytes per stage

    // staging: 128 rows x 2 16B-chunks (32 halves) ; 2 threads/row sc in {0,16}
    const int sr = t >> 1;                 // 0..127
    const int sc = (t & 1) << 4;           // 0 or 16

    auto stage = [&](int kt, int b) {
        const __half* Ab = A + (size_t)(m0 + sr) * K + kt * BK;
        const __half* Wb = W + (size_t)(n0 + sr) * K + kt * BK;
        unsigned ao = as_base + b * a_buf_stride + (unsigned)((sr * GSTR + sc) * 2);
        unsigned bo = bs_base + b * a_buf_stride + (unsigned)((sr * GSTR + sc) * 2);
        cp16(ao,      Ab + sc);
        cp16(ao + 16, Ab + sc + 8);
        cp16(bo,      Wb + sc);
        cp16(bo + 16, Wb + sc + 8);
    };

    float acc[4][4][4];
#pragma unroll
    for (int mi = 0; mi < 4; mi++)
#pragma unroll
        for (int ni = 0; ni < 4; ni++)
#pragma unroll
            for (int r = 0; r < 4; r++) acc[mi][ni][r] = 0.f;

    const int NKT = K / BK;
    stage(0, 0);
    cp_commit();

    int buf = 0;
    for (int kt = 0; kt < NKT; kt++) {
        cp_wait0();
        __syncthreads();
        if (kt + 1 < NKT) { stage(kt + 1, buf ^ 1); cp_commit(); }

#pragma unroll
        for (int ks = 0; ks < BK; ks += 16) {
            unsigned af[4][4], bf[4][2];
#pragma unroll
            for (int mi = 0; mi < 4; mi++) {
                unsigned addr = as_base + buf * a_buf_stride +
                    (unsigned)(((wm + mi * 16 + a_roff + mrr) * GSTR + ks + a_koff) * 2);
                ldsm_x4(af[mi][0], af[mi][1], af[mi][2], af[mi][3], addr);
            }
#pragma unroll
            for (int i = 0; i < 2; i++) {
                unsigned addr = bs_base + buf * a_buf_stride +
                    (unsigned)(((wn + (2 * i + ni_off) * 8 + mrr) * GSTR + ks + kh_off) * 2);
                ldsm_x4(bf[2 * i][0], bf[2 * i][1], bf[2 * i + 1][0], bf[2 * i + 1][1], addr);
            }
#pragma unroll
            for (int mi = 0; mi < 4; mi++)
#pragma unroll
                for (int ni = 0; ni < 4; ni++)
                    mma16(acc[mi][ni], af[mi], bf[ni]);
        }
        __syncthreads();
        buf ^= 1;
    }

#pragma unroll
    for (int mi = 0; mi < 4; mi++) {
        int r0 = m0 + wm + mi * 16 + gid;
#pragma unroll
        for (int ni = 0; ni < 4; ni++) {
            int c0 = n0 + wn + ni * 8 + 2 * tig;
            float b0 = bias[c0], b1 = bias[c0 + 1];
            if constexpr (HEADMAJOR) {
                int h = c0 >> 6, d = c0 & (DEPTH - 1);
#pragma unroll
                for (int rr = 0; rr < 2; rr++) {
                    int m = r0 + rr * 8;
                    int bb = m >> 11, s = m & (SEQ - 1);
                    __half* dst = (__half*)C +
                        (((size_t)(bb * NUM_HEADS + h)) * SEQ + s) * DEPTH + d;
                    *(unsigned*)dst = pack2(acc[mi][ni][rr * 2] + b0,
                                            acc[mi][ni][rr * 2 + 1] + b1);
                }
            } else {
                float* dst = (float*)C;
                *(float2*)&dst[(size_t)r0 * N + c0] =
                    make_float2(acc[mi][ni][0] + b0, acc[mi][ni][1] + b1);
                *(float2*)&dst[(size_t)(r0 + 8) * N + c0] =
                    make_float2(acc[mi][ni][2] + b0, acc[mi][ni][3] + b1);
            }
        }
    }
}

// ---------------------------------------------------------------------------
// Fused attention: warp-row layout, half-native, cp.async double-buffered
// K/V staging with 128-row stages processed as two 64-col chunks.
// ---------------------------------------------------------------------------
__global__ void __launch_bounds__(256, 2)
fused_attn(const __half* __restrict__ Q, const __half* __restrict__ Kmat,
           const __half* __restrict__ V, const float* __restrict__ mask,
           float* __restrict__ attn, __half* __restrict__ ctx)
{
    extern __shared__ __half dsm[];
    const unsigned ks_base = (unsigned)__cvta_generic_to_shared(dsm);
    const unsigned vs_base = ks_base + 2 * KBB * QSTR * 2;
    const unsigned buf_stride = KBB * QSTR * 2;   // bytes per stage

    const int bh = blockIdx.y;
    const int q0 = blockIdx.x * BQ;
    const __half* Qb = Q    + (size_t)bh * SEQ * DEPTH;
    const __half* Kb = Kmat + (size_t)bh * SEQ * DEPTH;
    const __half* Vb = V    + (size_t)bh * SEQ * DEPTH;
    float* attnb = attn + (size_t)bh * SEQ * SEQ;

    const int t = threadIdx.x;
    const int warp = t >> 5, lane = t & 31;
    const int gid = lane >> 2, tig = lane & 3;
    const int r0 = warp * 16 + gid;
    const int r1 = r0 + 8;

    const int mtx = lane >> 3;
    const int mrr = lane & 7;
    const int ni_off = mtx >> 1;
    const int kh_off = (mtx & 1) * 8;

    // staging: 128 rows x 64 halves ; 2 threads/row, sc in {0,32} halves,
    // each thread copies 4 16B chunks (+0,+8,+16,+24 halves) = 32 halves.
    const int sr = t >> 1;                 // 0..127
    const int sc = (t & 1) << 5;           // 0 / 32   (FIX: was <<4)

    auto stageK = [&](int kb, int b) {
        const __half* g = Kb + (size_t)(kb * KBB + sr) * DEPTH + sc;
        unsigned o = ks_base + b * buf_stride + (unsigned)((sr * QSTR + sc) * 2);
        cp16(o, g); cp16(o + 16, g + 8);
        cp16(o + 32, g + 16); cp16(o + 48, g + 24);
    };
    auto stageV = [&](int kb, int b) {
        const __half* g = Vb + (size_t)(kb * KBB + sr) * DEPTH + sc;
        unsigned o = vs_base + b * buf_stride + (unsigned)((sr * QSTR + sc) * 2);
        cp16(o, g); cp16(o + 16, g + 8);
        cp16(o + 32, g + 16); cp16(o + 48, g + 24);
    };

    // ---- Q fragments in registers for the whole kernel ----
    unsigned qf[4][4];
#pragma unroll
    for (int s = 0; s < 4; s++) {
        qf[s][0] = *(const unsigned*)&Qb[(size_t)(q0 + r0) * DEPTH + 16 * s + 2 * tig];
        qf[s][1] = *(const unsigned*)&Qb[(size_t)(q0 + r1) * DEPTH + 16 * s + 2 * tig];
        qf[s][2] = *(const unsigned*)&Qb[(size_t)(q0 + r0) * DEPTH + 16 * s + 8 + 2 * tig];
        qf[s][3] = *(const unsigned*)&Qb[(size_t)(q0 + r1) * DEPTH + 16 * s + 8 + 2 * tig];
    }

    const float* mrow0 = mask + (size_t)(q0 + r0) * SEQ;
    const float* mrow1 = mask + (size_t)(q0 + r1) * SEQ;

    float m0 = -1e30f, m1 = -1e30f, l0 = 0.f, l1 = 0.f;

    // ------------------------- Pass A: stats -------------------------
    stageK(0, 0);
    cp_commit();
    int buf = 0;
    for (int kb = 0; kb < NKB; kb++) {
        cp_wait0();
        __syncthreads();
        if (kb + 1 < NKB) { stageK(kb + 1, buf ^ 1); cp_commit(); }

#pragma unroll
        for (int ch = 0; ch < 2; ch++) {
            const int k0 = kb * KBB + ch * 64;
            const int rowoff = buf * KBB + ch * 64;

            float acc[8][4];
#pragma unroll
            for (int ni = 0; ni < 8; ni++)
#pragma unroll
                for (int r = 0; r < 4; r++) acc[ni][r] = 0.f;

#pragma unroll
            for (int s = 0; s < 4; s++) {
                unsigned bf[8][2];
#pragma unroll
                for (int i = 0; i < 4; i++) {
                    unsigned addr = ks_base +
                        (unsigned)(((rowoff + (2 * i + ni_off) * 8 + mrr) * QSTR
                                    + 16 * s + kh_off) * 2);
                    ldsm_x4(bf[2 * i][0], bf[2 * i][1], bf[2 * i + 1][0], bf[2 * i + 1][1], addr);
                }
#pragma unroll
                for (int ni = 0; ni < 8; ni++) mma16(acc[ni], qf[s], bf[ni]);
            }

            float rm0 = -1e30f, rm1 = -1e30f;
#pragma unroll
            for (int ni = 0; ni < 8; ni++) {
                int c = ni * 8 + 2 * tig;
                float2 mv0 = *(const float2*)&mrow0[k0 + c];
                float2 mv1 = *(const float2*)&mrow1[k0 + c];
                acc[ni][0] = acc[ni][0] * 0.125f + mv0.x * (-1e9f);
                acc[ni][1] = acc[ni][1] * 0.125f + mv0.y * (-1e9f);
                acc[ni][2] = acc[ni][2] * 0.125f + mv1.x * (-1e9f);
                acc[ni][3] = acc[ni][3] * 0.125f + mv1.y * (-1e9f);
                rm0 = fmaxf(rm0, fmaxf(acc[ni][0], acc[ni][1]));
                rm1 = fmaxf(rm1, fmaxf(acc[ni][2], acc[ni][3]));
            }
            rm0 = fmaxf(rm0, __shfl_xor_sync(0xffffffffu, rm0, 1));
            rm0 = fmaxf(rm0, __shfl_xor_sync(0xffffffffu, rm0, 2));
            rm1 = fmaxf(rm1, __shfl_xor_sync(0xffffffffu, rm1, 1));
            rm1 = fmaxf(rm1, __shfl_xor_sync(0xffffffffu, rm1, 2));

            float mn0 = fmaxf(m0, rm0), mn1 = fmaxf(m1, rm1);
            float sc0 = __expf(m0 - mn0), sc1 = __expf(m1 - mn1);
            m0 = mn0; m1 = mn1;

            float ts0 = 0.f, ts1 = 0.f;
#pragma unroll
            for (int ni = 0; ni < 8; ni++) {
                ts0 += __expf(acc[ni][0] - m0) + __expf(acc[ni][1] - m0);
                ts1 += __expf(acc[ni][2] - m1) + __expf(acc[ni][3] - m1);
            }
            ts0 += __shfl_xor_sync(0xffffffffu, ts0, 1);
            ts0 += __shfl_xor_sync(0xffffffffu, ts0, 2);
            ts1 += __shfl_xor_sync(0xffffffffu, ts1, 1);
            ts1 += __shfl_xor_sync(0xffffffffu, ts1, 2);

            l0 = l0 * sc0 + ts0;
            l1 = l1 * sc1 + ts1;
        }
        __syncthreads();
        buf ^= 1;
    }

    const float inv0 = 1.0f / l0;
    const float inv1 = 1.0f / l1;

    // ------------------------- Pass B: write + PV -------------------------
    float cacc[8][4];
#pragma unroll
    for (int ni = 0; ni < 8; ni++)
#pragma unroll
        for (int r = 0; r < 4; r++) cacc[ni][r] = 0.f;

    stageK(0, 0); stageV(0, 0);
    cp_commit();
    buf = 0;
    for (int kb = 0; kb < NKB; kb++) {
        cp_wait0();
        __syncthreads();
        if (kb + 1 < NKB) { stageK(kb + 1, buf ^ 1); stageV(kb + 1, buf ^ 1); cp_commit(); }

#pragma unroll
        for (int ch = 0; ch < 2; ch++) {
            const int k0 = kb * KBB + ch * 64;
            const int rowoff = buf * KBB + ch * 64;

            float acc[8][4];
#pragma unroll
            for (int ni = 0; ni < 8; ni++)
#pragma unroll
                for (int r = 0; r < 4; r++) acc[ni][r] = 0.f;

#pragma unroll
            for (int s = 0; s < 4; s++) {
                unsigned bf[8][2];
#pragma unroll
                for (int i = 0; i < 4; i++) {
                    unsigned addr = ks_base +
                        (unsigned)(((rowoff + (2 * i + ni_off) * 8 + mrr) * QSTR
                                    + 16 * s + kh_off) * 2);
                    ldsm_x4(bf[2 * i][0], bf[2 * i][1], bf[2 * i + 1][0], bf[2 * i + 1][1], addr);
                }
#pragma unroll
                for (int ni = 0; ni < 8; ni++) mma16(acc[ni], qf[s], bf[ni]);
            }

            unsigned pf[4][4];
#pragma unroll
            for (int ni = 0; ni < 8; ni++) {
                int c = ni * 8 + 2 * tig;
                int kg = k0 + c;
                float2 mv0 = *(const float2*)&mrow0[kg];
                float2 mv1 = *(const float2*)&mrow1[kg];
                float p00 = __expf(acc[ni][0] * 0.125f + mv0.x * (-1e9f) - m0) * inv0;
                float p01 = __expf(acc[ni][1] * 0.125f + mv0.y * (-1e9f) - m0) * inv0;
                float p10 = __expf(acc[ni][2] * 0.125f + mv1.x * (-1e9f) - m1) * inv1;
                float p11 = __expf(acc[ni][3] * 0.125f + mv1.y * (-1e9f) - m1) * inv1;
                *(float2*)&attnb[(size_t)(q0 + r0) * SEQ + kg] = make_float2(p00, p01);
                *(float2*)&attnb[(size_t)(q0 + r1) * SEQ + kg] = make_float2(p10, p11);
                int sp = ni >> 1;
                if (ni & 1) { pf[sp][2] = pack2(p00, p01); pf[sp][3] = pack2(p10, p11); }
                else        { pf[sp][0] = pack2(p00, p01); pf[sp][1] = pack2(p10, p11); }
            }

#pragma unroll
            for (int s = 0; s < 4; s++) {
                unsigned vbf[8][2];
#pragma unroll
                for (int i = 0; i < 4; i++) {
                    unsigned addr = vs_base +
                        (unsigned)(((rowoff + 16 * s + kh_off + mrr) * QSTR
                                    + (2 * i + ni_off) * 8) * 2);
                    ldsm_x4_t(vbf[2 * i][0], vbf[2 * i][1], vbf[2 * i + 1][0], vbf[2 * i + 1][1], addr);
                }
#pragma unroll
                for (int ni = 0; ni < 8; ni++) mma16(cacc[ni], pf[s], vbf[ni]);
            }
        }
        __syncthreads();
        buf ^= 1;
    }

    const int b = bh >> 4;
    const int hh = bh & 15;
#pragma unroll
    for (int ni = 0; ni < 8; ni++) {
        int d0 = ni * 8 + 2 * tig;
        *(unsigned*)&ctx[((size_t)b * SEQ + q0 + r0) * D_MODEL + hh * DEPTH + d0] =
            pack2(cacc[ni][0], cacc[ni][1]);
        *(unsigned*)&ctx[((size_t)b * SEQ + q0 + r1) * D_MODEL + hh * DEPTH + d0] =
            pack2(cacc[ni][2], cacc[ni][3]);
    }
}

// ---------------------------------------------------------------------------
// Inputs (metadata order): v, k, q, mask, wq_w, wq_b, wk_w, wk_b, wv_w, wv_b,
//                          dense_w, dense_b
// Output: [out (B*S*D_MODEL) | attn (B*H*S*S)] fp32
// ---------------------------------------------------------------------------
extern "C" void kernel_launch(void* const* d_in, const int* in_sizes, int n_in,
                              void* d_out, int out_size)
{
    const float* v_in = (const float*)d_in[0];
    const float* k_in = (const float*)d_in[1];
    const float* q_in = (const float*)d_in[2];
    const float* mask = (const float*)d_in[3];
    const float* wq_w = (const float*)d_in[4];
    const float* wq_b = (const float*)d_in[5];
    const float* wk_w = (const float*)d_in[6];
    const float* wk_b = (const float*)d_in[7];
    const float* wv_w = (const float*)d_in[8];
    const float* wv_b = (const float*)d_in[9];
    const float* dw   = (const float*)d_in[10];
    const float* db   = (const float*)d_in[11];

    float* out  = (float*)d_out;
    float* attn = out + (size_t)BATCH * SEQ * D_MODEL;

    __half *gq, *gk, *gv, *gctx, *gxh, *gwh;
    cudaGetSymbolAddress((void**)&gq,   g_Q);
    cudaGetSymbolAddress((void**)&gk,   g_K);
    cudaGetSymbolAddress((void**)&gv,   g_V);
    cudaGetSymbolAddress((void**)&gctx, g_CTX);
    cudaGetSymbolAddress((void**)&gxh,  g_XH);
    cudaGetSymbolAddress((void**)&gwh,  g_WH);

    const size_t XN = (size_t)MTOT * D_MODEL;      // 8388608
    const size_t WN = (size_t)D_MODEL * D_MODEL;   // 1048576
    __half* xh_v = gxh;
    __half* xh_k = gxh + XN;
    __half* xh_q = gxh + 2 * XN;
    __half* wh_q = gwh;
    __half* wh_k = gwh + WN;
    __half* wh_v = gwh + 2 * WN;
    __half* wh_d = gwh + 3 * WN;

    ConvJobs jobs;
    jobs.src[0] = v_in;  jobs.dst[0] = xh_v; jobs.n[0] = (int)XN;
    jobs.src[1] = k_in;  jobs.dst[1] = xh_k; jobs.n[1] = (int)XN;
    jobs.src[2] = q_in;  jobs.dst[2] = xh_q; jobs.n[2] = (int)XN;
    jobs.src[3] = wq_w;  jobs.dst[3] = wh_q; jobs.n[3] = (int)WN;
    jobs.src[4] = wk_w;  jobs.dst[4] = wh_k; jobs.n[4] = (int)WN;
    jobs.src[5] = wv_w;  jobs.dst[5] = wh_v; jobs.n[5] = (int)WN;
    jobs.src[6] = dw;    jobs.dst[6] = wh_d; jobs.n[6] = (int)WN;

    dim3 gcv(1024, 1, 7);
    convert_f2h<<<gcv, 256>>>(jobs);

    dim3 gp(D_MODEL / 128, MTOT / 128);   // (8, 64)
    gemm_f16<1, __half><<<gp, 256>>>(xh_q, wh_q, wq_b, gq, MTOT, D_MODEL, D_MODEL);
    gemm_f16<1, __half><<<gp, 256>>>(xh_k, wh_k, wk_b, gk, MTOT, D_MODEL, D_MODEL);
    gemm_f16<1, __half><<<gp, 256>>>(xh_v, wh_v, wv_b, gv, MTOT, D_MODEL, D_MODEL);

    const int fsmem = 2 * 2 * KBB * QSTR * (int)sizeof(__half);  // 73728
    cudaFuncSetAttribute(fused_attn, cudaFuncAttributeMaxDynamicSharedMemorySize, fsmem);
    dim3 gf(SEQ / BQ, BHN);               // (16, 64)
    fused_attn<<<gf, 256, fsmem>>>(gq, gk, gv, mask, attn, gctx);

    gemm_f16<0, float><<<gp, 256>>>(gctx, wh_d, db, out, MTOT, D_MODEL, D_MODEL);
}